// round 2
// baseline (speedup 1.0000x reference)
#include <cuda_runtime.h>
#include <math.h>

// Problem constants
#define BATCH 256
#define TLEN  512
#define DIM   1024
#define VOCAB 32000

// Step-GEMM tiling inside the persistent kernel:
// grid = 256 CTAs; CTA bid -> GEMM tile (kc = bid>>5, nc = bid&31), LN row b = bid
#define NK 8
#define NN 32
#define KT (DIM / NK)   // 128
#define NT (DIM / NN)   // 32
#define NCTA 256

// Logits tiling
#define VT 128
#define BT 32

// ---------------------------------------------------------------------------
// Device scratch (static — no cudaMalloc allowed)
// ---------------------------------------------------------------------------
__device__ float g_P[NK][BATCH][DIM];   // 8 MB partial sums (lives in L2)
__device__ float g_UT[DIM][BATCH];      // current u, transposed (K-major)
__device__ float g_HT[DIM][BATCH];      // transposed hidden_state
__device__ unsigned g_bar_arrive = 0;
__device__ unsigned g_bar_gen    = 0;

// ---------------------------------------------------------------------------
// Grid-wide barrier (sense-reversing, all 256 CTAs co-resident by construction)
// ---------------------------------------------------------------------------
__device__ __forceinline__ void grid_barrier()
{
    __threadfence();          // make this thread's global stores L2-visible
    __syncthreads();
    if (threadIdx.x == 0) {
        unsigned gen = *(volatile unsigned*)&g_bar_gen;
        if (atomicAdd(&g_bar_arrive, 1u) == NCTA - 1u) {
            atomicExch(&g_bar_arrive, 0u);
            __threadfence();
            atomicAdd(&g_bar_gen, 1u);     // release
        } else {
            while (*(volatile unsigned*)&g_bar_gen == gen) { }
        }
        __threadfence();      // acquire side
    }
    __syncthreads();
}

// ---------------------------------------------------------------------------
// One GEMM tile: P[kc][b][n0..n0+31] += over K-tile [k0, k0+128)
// src is [DIM][BATCH] (K-major), W tile already resident in sW.
// ---------------------------------------------------------------------------
__device__ __forceinline__ void gemm_tile(
    const float* __restrict__ src,
    float (&sW)[KT][NT], float (&sU)[16][BATCH],
    int k0, int n0, int kc, int tid)
{
    const int nb = tid & 15;   // n-pair: n0 + 2*nb, +1
    const int bg = tid >> 4;   // b-group: b = bg*16 .. +15

    float acc[16][2];
    #pragma unroll
    for (int i = 0; i < 16; ++i) { acc[i][0] = 0.f; acc[i][1] = 0.f; }

    for (int slab = 0; slab < KT / 16; ++slab) {
        __syncthreads();
        #pragma unroll
        for (int i = 0; i < 4; ++i) {
            int idx = tid * 4 + i * 1024;
            int r = idx >> 8, c = idx & 255;
            float4 v = __ldcg((const float4*)&src[(size_t)(k0 + slab * 16 + r) * BATCH + c]);
            *(float4*)&sU[r][c] = v;
        }
        __syncthreads();

        #pragma unroll
        for (int kk = 0; kk < 16; ++kk) {
            const int k = slab * 16 + kk;
            const float2 w  = *(const float2*)&sW[k][nb * 2];
            const float4 u0 = *(const float4*)&sU[kk][bg * 16 + 0];
            const float4 u1 = *(const float4*)&sU[kk][bg * 16 + 4];
            const float4 u2 = *(const float4*)&sU[kk][bg * 16 + 8];
            const float4 u3 = *(const float4*)&sU[kk][bg * 16 + 12];
            float us[16] = {u0.x,u0.y,u0.z,u0.w, u1.x,u1.y,u1.z,u1.w,
                            u2.x,u2.y,u2.z,u2.w, u3.x,u3.y,u3.z,u3.w};
            #pragma unroll
            for (int i = 0; i < 16; ++i) {
                acc[i][0] = fmaf(us[i], w.x, acc[i][0]);
                acc[i][1] = fmaf(us[i], w.y, acc[i][1]);
            }
        }
    }

    #pragma unroll
    for (int i = 0; i < 16; ++i) {
        float2 v = make_float2(acc[i][0], acc[i][1]);
        __stcg((float2*)&g_P[kc][bg * 16 + i][n0 + nb * 2], v);
    }
}

// ---------------------------------------------------------------------------
// Persistent scan kernel: init + c-precompute + 512 steps of (GEMM, LN)
// ---------------------------------------------------------------------------
__global__ __launch_bounds__(256, 2) void rnn_persistent(
    const float* __restrict__ hidden, const int* __restrict__ tok,
    const float* __restrict__ emb,    const float* __restrict__ Wdt,
    const float* __restrict__ bdt,    const float* __restrict__ gamma,
    const float* __restrict__ beta,   float* __restrict__ zout)
{
    __shared__ float sW[KT][NT];     // 16 KB — W tile (persistent across steps)
    __shared__ float sU[16][BATCH];  // 16 KB — activation slab
    __shared__ float red[2][8];

    const int tid = threadIdx.x;
    const int bid = blockIdx.x;
    const int nc  = bid & 31,  kc = bid >> 5;
    const int n0  = nc * NT,   k0 = kc * KT;
    const int b   = bid;          // LN role: batch row
    const int d0  = tid * 4;      // LN role: this thread's 4 channels

    // ---- init: transpose hidden into g_HT; u0 = emb[token[:,0]] into g_UT ----
    {
        #pragma unroll
        for (int i = 0; i < 4; ++i) {
            int d = tid + i * 256;
            g_HT[d][b] = hidden[(size_t)b * DIM + d];
        }
        const int tk0 = tok[(size_t)b * TLEN];
        #pragma unroll
        for (int i = 0; i < 4; ++i) {
            int d = tid + i * 256;
            g_UT[d][b] = emb[(size_t)tk0 * DIM + d];
        }
    }

    // u row for this CTA's batch row (registers, persistent over the scan)
    float4 ureg;
    {
        const int tk0 = tok[(size_t)b * TLEN];
        ureg = *(const float4*)&emb[(size_t)tk0 * DIM + d0];
    }
    const float4 g4 = *(const float4*)&gamma[d0];
    const float4 b4 = *(const float4*)&beta[d0];

    // ---- c = hidden @ W_bot + b_dt (precompute; W_bot = rows D..2D-1) ----
    // load W_bot tile
    #pragma unroll
    for (int idx = tid; idx < KT * NT; idx += 256) {
        int k = idx >> 5, n = idx & 31;
        sW[k][n] = Wdt[(size_t)(DIM + k0 + k) * DIM + n0 + n];
    }
    grid_barrier();                    // g_HT complete everywhere
    gemm_tile(&g_HT[0][0], sW, sU, k0, n0, kc, tid);
    grid_barrier();                    // g_P complete

    float4 creg = *(const float4*)&bdt[d0];
    #pragma unroll
    for (int j = 0; j < NK; ++j) {
        float4 p = __ldcg((const float4*)&g_P[j][b][d0]);
        creg.x += p.x; creg.y += p.y; creg.z += p.z; creg.w += p.w;
    }

    // load W_top tile (persistent for all 512 steps)
    __syncthreads();
    #pragma unroll
    for (int idx = tid; idx < KT * NT; idx += 256) {
        int k = idx >> 5, n = idx & 31;
        sW[k][n] = Wdt[(size_t)(k0 + k) * DIM + n0 + n];
    }
    grid_barrier();                    // everyone done reading P before loop overwrites

    // ---- scan ----
    for (int t = 0; t < TLEN; ++t) {
        gemm_tile(&g_UT[0][0], sW, sU, k0, n0, kc, tid);
        grid_barrier();

        // LN role: y = C + U + sum_j P[j]
        float4 y = creg;
        y.x += ureg.x; y.y += ureg.y; y.z += ureg.z; y.w += ureg.w;
        #pragma unroll
        for (int j = 0; j < NK; ++j) {
            float4 p = __ldcg((const float4*)&g_P[j][b][d0]);
            y.x += p.x; y.y += p.y; y.z += p.z; y.w += p.w;
        }

        float s1 = y.x + y.y + y.z + y.w;
        float s2 = y.x*y.x + y.y*y.y + y.z*y.z + y.w*y.w;
        #pragma unroll
        for (int o = 16; o; o >>= 1) {
            s1 += __shfl_xor_sync(0xffffffffu, s1, o);
            s2 += __shfl_xor_sync(0xffffffffu, s2, o);
        }
        if ((tid & 31) == 0) { red[0][tid >> 5] = s1; red[1][tid >> 5] = s2; }
        __syncthreads();
        float t1 = 0.f, t2 = 0.f;
        #pragma unroll
        for (int j = 0; j < 8; ++j) { t1 += red[0][j]; t2 += red[1][j]; }
        __syncthreads();

        const float mean = t1 * (1.f / DIM);
        const float var  = t2 * (1.f / DIM) - mean * mean;
        const float rstd = rsqrtf(var + 1e-5f);

        float4 s;
        s.x = (y.x - mean) * rstd * g4.x + b4.x;
        s.y = (y.y - mean) * rstd * g4.y + b4.y;
        s.z = (y.z - mean) * rstd * g4.z + b4.z;
        s.w = (y.w - mean) * rstd * g4.w + b4.w;

        if (t < TLEN - 1) {
            const int tk = tok[(size_t)b * TLEN + t + 1];
            const float4 e = *(const float4*)&emb[(size_t)tk * DIM + d0];
            ureg.x = s.x + e.x; ureg.y = s.y + e.y;
            ureg.z = s.z + e.z; ureg.w = s.w + e.w;
            __stcg(&g_UT[d0 + 0][b], ureg.x);
            __stcg(&g_UT[d0 + 1][b], ureg.y);
            __stcg(&g_UT[d0 + 2][b], ureg.z);
            __stcg(&g_UT[d0 + 3][b], ureg.w);
        } else {
            *(float4*)&zout[(size_t)b * DIM + d0] = s;
        }
        grid_barrier();
    }
}

// ---------------------------------------------------------------------------
// Logits: L[b][v] = sum_d z[b][d] * Wv[d][v] + bv[v]
// ---------------------------------------------------------------------------
__global__ __launch_bounds__(256, 2) void logits_kernel(
    const float* __restrict__ z, const float* __restrict__ Wv,
    const float* __restrict__ bv, float* __restrict__ L)
{
    __shared__ float sS[BT][64];     // 8 KB
    __shared__ float sWv[64][VT];    // 32 KB

    const int tid = threadIdx.x;
    const int v0  = blockIdx.x * VT;
    const int b0  = blockIdx.y * BT;
    const int vb  = tid & 31;
    const int bg  = tid >> 5;

    float acc[4][4] = {};

    for (int slab = 0; slab < DIM / 64; ++slab) {
        const int d0 = slab * 64;
        __syncthreads();
        for (int idx = tid; idx < BT * 64; idx += 256)
            sS[idx >> 6][idx & 63] = z[(size_t)(b0 + (idx >> 6)) * DIM + d0 + (idx & 63)];
        for (int idx = tid; idx < 64 * VT; idx += 256)
            sWv[idx >> 7][idx & 127] = Wv[(size_t)(d0 + (idx >> 7)) * VOCAB + v0 + (idx & 127)];
        __syncthreads();

        #pragma unroll 4
        for (int d = 0; d < 64; ++d) {
            const float4 w = *(const float4*)&sWv[d][vb * 4];
            float u0 = sS[bg * 4 + 0][d];
            float u1 = sS[bg * 4 + 1][d];
            float u2 = sS[bg * 4 + 2][d];
            float u3 = sS[bg * 4 + 3][d];
            acc[0][0] = fmaf(u0, w.x, acc[0][0]); acc[0][1] = fmaf(u0, w.y, acc[0][1]);
            acc[0][2] = fmaf(u0, w.z, acc[0][2]); acc[0][3] = fmaf(u0, w.w, acc[0][3]);
            acc[1][0] = fmaf(u1, w.x, acc[1][0]); acc[1][1] = fmaf(u1, w.y, acc[1][1]);
            acc[1][2] = fmaf(u1, w.z, acc[1][2]); acc[1][3] = fmaf(u1, w.w, acc[1][3]);
            acc[2][0] = fmaf(u2, w.x, acc[2][0]); acc[2][1] = fmaf(u2, w.y, acc[2][1]);
            acc[2][2] = fmaf(u2, w.z, acc[2][2]); acc[2][3] = fmaf(u2, w.w, acc[2][3]);
            acc[3][0] = fmaf(u3, w.x, acc[3][0]); acc[3][1] = fmaf(u3, w.y, acc[3][1]);
            acc[3][2] = fmaf(u3, w.z, acc[3][2]); acc[3][3] = fmaf(u3, w.w, acc[3][3]);
        }
    }

    const float4 bvv = *(const float4*)&bv[v0 + vb * 4];
    #pragma unroll
    for (int i = 0; i < 4; ++i) {
        float4 r = make_float4(acc[i][0] + bvv.x, acc[i][1] + bvv.y,
                               acc[i][2] + bvv.z, acc[i][3] + bvv.w);
        *(float4*)&L[(size_t)(b0 + bg * 4 + i) * VOCAB + v0 + vb * 4] = r;
    }
}

// ---------------------------------------------------------------------------
// In-place log_softmax over each row of L [BATCH][VOCAB]
// ---------------------------------------------------------------------------
__global__ __launch_bounds__(256) void logsoftmax_kernel(float* __restrict__ L)
{
    const int b   = blockIdx.x;
    const int tid = threadIdx.x;
    float* row = L + (size_t)b * VOCAB;
    __shared__ float red[8];

    float m = -1e30f;
    for (int i = tid * 4; i < VOCAB; i += 1024) {
        const float4 v = *(const float4*)&row[i];
        m = fmaxf(m, fmaxf(fmaxf(v.x, v.y), fmaxf(v.z, v.w)));
    }
    #pragma unroll
    for (int o = 16; o; o >>= 1) m = fmaxf(m, __shfl_xor_sync(0xffffffffu, m, o));
    if ((tid & 31) == 0) red[tid >> 5] = m;
    __syncthreads();
    float M = red[0];
    #pragma unroll
    for (int j = 1; j < 8; ++j) M = fmaxf(M, red[j]);
    __syncthreads();

    float s = 0.f;
    for (int i = tid * 4; i < VOCAB; i += 1024) {
        const float4 v = *(const float4*)&row[i];
        s += expf(v.x - M) + expf(v.y - M) + expf(v.z - M) + expf(v.w - M);
    }
    #pragma unroll
    for (int o = 16; o; o >>= 1) s += __shfl_xor_sync(0xffffffffu, s, o);
    if ((tid & 31) == 0) red[tid >> 5] = s;
    __syncthreads();
    float S = 0.f;
    #pragma unroll
    for (int j = 0; j < 8; ++j) S += red[j];
    const float lse = M + logf(S);

    for (int i = tid * 4; i < VOCAB; i += 1024) {
        float4 v = *(const float4*)&row[i];
        v.x -= lse; v.y -= lse; v.z -= lse; v.w -= lse;
        *(float4*)&row[i] = v;
    }
}

// ---------------------------------------------------------------------------
// kernel_launch — 3 graph nodes total
// Inputs: 0 hidden [B,1,D] | 1 tokens [B,T] int | 2 emb_out [V,D] | 3 W_dt [2D,D]
//         4 b_dt [D] | 5 gamma [D] | 6 beta [D] | 7 W_v [D,V] | 8 b_v [V]
// Output: [ z (B*D) | y (B*V) ] f32
// ---------------------------------------------------------------------------
extern "C" void kernel_launch(void* const* d_in, const int* in_sizes, int n_in,
                              void* d_out, int out_size)
{
    const float* hidden = (const float*)d_in[0];
    const int*   tok    = (const int*)  d_in[1];
    const float* emb    = (const float*)d_in[2];
    const float* Wdt    = (const float*)d_in[3];
    const float* bdt    = (const float*)d_in[4];
    const float* gamma  = (const float*)d_in[5];
    const float* beta   = (const float*)d_in[6];
    const float* Wv     = (const float*)d_in[7];
    const float* bv     = (const float*)d_in[8];

    float* zout = (float*)d_out;
    float* yout = zout + (size_t)BATCH * DIM;

    rnn_persistent<<<NCTA, 256>>>(hidden, tok, emb, Wdt, bdt, gamma, beta, zout);
    logits_kernel<<<dim3(VOCAB / VT, BATCH / BT), 256>>>(zout, Wv, bv, yout);
    logsoftmax_kernel<<<BATCH, 256>>>(yout);
}

// round 4
// speedup vs baseline: 1.0477x; 1.0477x over previous
#include <cuda_runtime.h>
#include <math.h>

// Problem constants
#define BATCH 256
#define TLEN  512
#define DIM   1024
#define VOCAB 32000

// Step-GEMM tiling inside the persistent kernel:
// grid = 256 CTAs; CTA bid -> GEMM tile (kc = bid>>5, nc = bid&31), LN row b = bid
#define NK 8
#define NN 32
#define KT (DIM / NK)   // 128
#define NT (DIM / NN)   // 32
#define NCTA 256

// Logits tiling
#define VT 128
#define BT 32

// ---------------------------------------------------------------------------
// Device scratch (static — no cudaMalloc allowed)
// ---------------------------------------------------------------------------
__device__ float g_P[NK][BATCH][DIM];   // 8 MB partial sums (lives in L2)
__device__ float g_UT[DIM][BATCH];      // current u, transposed (K-major)
__device__ float g_HT[DIM][BATCH];      // transposed hidden_state
__device__ unsigned g_bar_arrive = 0;
__device__ unsigned g_bar_gen    = 0;

// ---------------------------------------------------------------------------
// Packed f32x2 helpers (Blackwell FFMA2 — only reachable via PTX)
// ---------------------------------------------------------------------------
__device__ __forceinline__ unsigned long long pack2(float lo, float hi)
{
    unsigned long long r;
    asm("mov.b64 %0, {%1, %2};" : "=l"(r) : "f"(lo), "f"(hi));
    return r;
}
__device__ __forceinline__ float2 unpack2(unsigned long long v)
{
    float2 r;
    asm("mov.b64 {%0, %1}, %2;" : "=f"(r.x), "=f"(r.y) : "l"(v));
    return r;
}
__device__ __forceinline__ void ffma2(unsigned long long& acc,
                                      unsigned long long a,
                                      unsigned long long b)
{
    asm("fma.rn.f32x2 %0, %1, %2, %0;" : "+l"(acc) : "l"(a), "l"(b));
}

// ---------------------------------------------------------------------------
// Grid-wide barrier (sense-reversing, all 256 CTAs co-resident by construction)
// ---------------------------------------------------------------------------
__device__ __forceinline__ void grid_barrier()
{
    __threadfence();
    __syncthreads();
    if (threadIdx.x == 0) {
        unsigned gen = *(volatile unsigned*)&g_bar_gen;
        if (atomicAdd(&g_bar_arrive, 1u) == NCTA - 1u) {
            atomicExch(&g_bar_arrive, 0u);
            __threadfence();
            atomicAdd(&g_bar_gen, 1u);     // release
        } else {
            while (*(volatile unsigned*)&g_bar_gen == gen) { }
        }
        __threadfence();
    }
    __syncthreads();
}

// ---------------------------------------------------------------------------
// One GEMM tile: P[kc][b][n0..n0+31] = sum over K-tile [k0, k0+128)
// src is [DIM][BATCH] (K-major), W tile already resident in sW.
// FFMA2 inner loop: batch pairs packed in f32x2 lanes.
// ---------------------------------------------------------------------------
__device__ __forceinline__ void gemm_tile(
    const float* __restrict__ src,
    float (&sW)[KT][NT], float (&sU)[16][BATCH],
    int k0, int n0, int kc, int tid)
{
    const int nb = tid & 15;          // n-pair: n0 + 2*nb, +1
    const int bg = tid >> 4;          // b-group: b = bg*16 .. +15
    const int pr = tid >> 6;          // prefetch row base (0..3)
    const int pc = (tid * 4) & 255;   // prefetch col (float4)

    unsigned long long ax[8], ay[8];
    #pragma unroll
    for (int j = 0; j < 8; ++j) { ax[j] = 0ull; ay[j] = 0ull; }

    // prefetch slab 0
    float4 pf[4];
    #pragma unroll
    for (int i = 0; i < 4; ++i)
        pf[i] = __ldcg((const float4*)&src[(size_t)(k0 + pr + i * 4) * BATCH + pc]);

    for (int slab = 0; slab < KT / 16; ++slab) {
        __syncthreads();
        #pragma unroll
        for (int i = 0; i < 4; ++i)
            *(float4*)&sU[pr + i * 4][pc] = pf[i];
        __syncthreads();

        // issue next slab's loads early — latency hides under compute
        if (slab + 1 < KT / 16) {
            #pragma unroll
            for (int i = 0; i < 4; ++i)
                pf[i] = __ldcg((const float4*)&src[
                    (size_t)(k0 + (slab + 1) * 16 + pr + i * 4) * BATCH + pc]);
        }

        #pragma unroll
        for (int kk = 0; kk < 16; ++kk) {
            const float2 w = *(const float2*)&sW[slab * 16 + kk][nb * 2];
            const unsigned long long wxx = pack2(w.x, w.x);
            const unsigned long long wyy = pack2(w.y, w.y);
            const ulonglong2* up = (const ulonglong2*)&sU[kk][bg * 16];
            #pragma unroll
            for (int q = 0; q < 4; ++q) {
                const ulonglong2 u = up[q];
                ffma2(ax[q * 2 + 0], u.x, wxx);
                ffma2(ay[q * 2 + 0], u.x, wyy);
                ffma2(ax[q * 2 + 1], u.y, wxx);
                ffma2(ay[q * 2 + 1], u.y, wyy);
            }
        }
    }

    #pragma unroll
    for (int j = 0; j < 8; ++j) {
        const float2 x = unpack2(ax[j]);   // batches (2j, 2j+1), col even
        const float2 y = unpack2(ay[j]);   // batches (2j, 2j+1), col odd
        __stcg((float2*)&g_P[kc][bg * 16 + 2 * j + 0][n0 + nb * 2],
               make_float2(x.x, y.x));
        __stcg((float2*)&g_P[kc][bg * 16 + 2 * j + 1][n0 + nb * 2],
               make_float2(x.y, y.y));
    }
}

// ---------------------------------------------------------------------------
// Persistent scan kernel: init + c-precompute + 512 steps of (GEMM, LN)
// ---------------------------------------------------------------------------
__global__ __launch_bounds__(256, 2) void rnn_persistent(
    const float* __restrict__ hidden, const int* __restrict__ tok,
    const float* __restrict__ emb,    const float* __restrict__ Wdt,
    const float* __restrict__ bdt,    const float* __restrict__ gamma,
    const float* __restrict__ beta,   float* __restrict__ zout)
{
    __shared__ float sW[KT][NT];     // 16 KB — W tile (persistent across steps)
    __shared__ float sU[16][BATCH];  // 16 KB — activation slab
    __shared__ float red[2][8];

    const int tid = threadIdx.x;
    const int bid = blockIdx.x;
    const int nc  = bid & 31,  kc = bid >> 5;
    const int n0  = nc * NT,   k0 = kc * KT;
    const int b   = bid;          // LN role: batch row
    const int d0  = tid * 4;      // LN role: this thread's 4 channels

    // ---- init: transpose hidden into g_HT; u0 = emb[token[:,0]] into g_UT ----
    {
        #pragma unroll
        for (int i = 0; i < 4; ++i) {
            int d = tid + i * 256;
            g_HT[d][b] = hidden[(size_t)b * DIM + d];
        }
        const int tk0 = tok[(size_t)b * TLEN];
        #pragma unroll
        for (int i = 0; i < 4; ++i) {
            int d = tid + i * 256;
            g_UT[d][b] = emb[(size_t)tk0 * DIM + d];
        }
    }

    // u row for this CTA's batch row (registers, persistent over the scan)
    float4 ureg;
    {
        const int tk0 = tok[(size_t)b * TLEN];
        ureg = *(const float4*)&emb[(size_t)tk0 * DIM + d0];
    }
    const float4 g4 = *(const float4*)&gamma[d0];
    const float4 b4 = *(const float4*)&beta[d0];

    // ---- c = hidden @ W_bot + b_dt (precompute; W_bot = rows D..2D-1) ----
    #pragma unroll
    for (int idx = tid; idx < KT * NT; idx += 256) {
        int k = idx >> 5, n = idx & 31;
        sW[k][n] = Wdt[(size_t)(DIM + k0 + k) * DIM + n0 + n];
    }
    grid_barrier();                    // g_HT complete everywhere
    gemm_tile(&g_HT[0][0], sW, sU, k0, n0, kc, tid);
    grid_barrier();                    // g_P complete

    float4 creg = *(const float4*)&bdt[d0];
    #pragma unroll
    for (int j = 0; j < NK; ++j) {
        float4 p = __ldcg((const float4*)&g_P[j][b][d0]);
        creg.x += p.x; creg.y += p.y; creg.z += p.z; creg.w += p.w;
    }

    // load W_top tile (persistent for all 512 steps)
    __syncthreads();
    #pragma unroll
    for (int idx = tid; idx < KT * NT; idx += 256) {
        int k = idx >> 5, n = idx & 31;
        sW[k][n] = Wdt[(size_t)(k0 + k) * DIM + n0 + n];
    }
    grid_barrier();                    // everyone done reading P before loop overwrites

    // ---- scan ----
    for (int t = 0; t < TLEN; ++t) {
        gemm_tile(&g_UT[0][0], sW, sU, k0, n0, kc, tid);
        grid_barrier();

        // LN role: y = C + U + sum_j P[j]
        float4 y = creg;
        y.x += ureg.x; y.y += ureg.y; y.z += ureg.z; y.w += ureg.w;
        #pragma unroll
        for (int j = 0; j < NK; ++j) {
            float4 p = __ldcg((const float4*)&g_P[j][b][d0]);
            y.x += p.x; y.y += p.y; y.z += p.z; y.w += p.w;
        }

        float s1 = y.x + y.y + y.z + y.w;
        float s2 = y.x*y.x + y.y*y.y + y.z*y.z + y.w*y.w;
        #pragma unroll
        for (int o = 16; o; o >>= 1) {
            s1 += __shfl_xor_sync(0xffffffffu, s1, o);
            s2 += __shfl_xor_sync(0xffffffffu, s2, o);
        }
        if ((tid & 31) == 0) { red[0][tid >> 5] = s1; red[1][tid >> 5] = s2; }
        __syncthreads();
        float t1 = 0.f, t2 = 0.f;
        #pragma unroll
        for (int j = 0; j < 8; ++j) { t1 += red[0][j]; t2 += red[1][j]; }
        __syncthreads();

        const float mean = t1 * (1.f / DIM);
        const float var  = t2 * (1.f / DIM) - mean * mean;
        const float rstd = rsqrtf(var + 1e-5f);

        float4 s;
        s.x = (y.x - mean) * rstd * g4.x + b4.x;
        s.y = (y.y - mean) * rstd * g4.y + b4.y;
        s.z = (y.z - mean) * rstd * g4.z + b4.z;
        s.w = (y.w - mean) * rstd * g4.w + b4.w;

        if (t < TLEN - 1) {
            const int tk = tok[(size_t)b * TLEN + t + 1];
            const float4 e = *(const float4*)&emb[(size_t)tk * DIM + d0];
            ureg.x = s.x + e.x; ureg.y = s.y + e.y;
            ureg.z = s.z + e.z; ureg.w = s.w + e.w;
            __stcg(&g_UT[d0 + 0][b], ureg.x);
            __stcg(&g_UT[d0 + 1][b], ureg.y);
            __stcg(&g_UT[d0 + 2][b], ureg.z);
            __stcg(&g_UT[d0 + 3][b], ureg.w);
        } else {
            *(float4*)&zout[(size_t)b * DIM + d0] = s;
        }
        grid_barrier();
    }
}

// ---------------------------------------------------------------------------
// Logits: L[b][v] = sum_d z[b][d] * Wv[d][v] + bv[v]   (FFMA2 over v-pairs)
// ---------------------------------------------------------------------------
__global__ __launch_bounds__(256, 2) void logits_kernel(
    const float* __restrict__ z, const float* __restrict__ Wv,
    const float* __restrict__ bv, float* __restrict__ L)
{
    __shared__ float sS[BT][64];     // 8 KB
    __shared__ float sWv[64][VT];    // 32 KB

    const int tid = threadIdx.x;
    const int v0  = blockIdx.x * VT;
    const int b0  = blockIdx.y * BT;
    const int vb  = tid & 31;
    const int bg  = tid >> 5;

    unsigned long long acc[4][2];
    #pragma unroll
    for (int i = 0; i < 4; ++i) { acc[i][0] = 0ull; acc[i][1] = 0ull; }

    for (int slab = 0; slab < DIM / 64; ++slab) {
        const int d0 = slab * 64;
        __syncthreads();
        for (int idx = tid; idx < BT * 64; idx += 256)
            sS[idx >> 6][idx & 63] = z[(size_t)(b0 + (idx >> 6)) * DIM + d0 + (idx & 63)];
        for (int idx = tid; idx < 64 * VT; idx += 256)
            sWv[idx >> 7][idx & 127] = Wv[(size_t)(d0 + (idx >> 7)) * VOCAB + v0 + (idx & 127)];
        __syncthreads();

        #pragma unroll 4
        for (int d = 0; d < 64; ++d) {
            const ulonglong2 w2 = *(const ulonglong2*)&sWv[d][vb * 4];
            #pragma unroll
            for (int i = 0; i < 4; ++i) {
                const float u = sS[bg * 4 + i][d];
                const unsigned long long uu = pack2(u, u);
                ffma2(acc[i][0], uu, w2.x);
                ffma2(acc[i][1], uu, w2.y);
            }
        }
    }

    const float4 bvv = *(const float4*)&bv[v0 + vb * 4];
    #pragma unroll
    for (int i = 0; i < 4; ++i) {
        const float2 p0 = unpack2(acc[i][0]);
        const float2 p1 = unpack2(acc[i][1]);
        float4 r = make_float4(p0.x + bvv.x, p0.y + bvv.y,
                               p1.x + bvv.z, p1.y + bvv.w);
        *(float4*)&L[(size_t)(b0 + bg * 4 + i) * VOCAB + v0 + vb * 4] = r;
    }
}

// ---------------------------------------------------------------------------
// In-place log_softmax over each row of L [BATCH][VOCAB]
// ---------------------------------------------------------------------------
__global__ __launch_bounds__(256) void logsoftmax_kernel(float* __restrict__ L)
{
    const int b   = blockIdx.x;
    const int tid = threadIdx.x;
    float* row = L + (size_t)b * VOCAB;
    __shared__ float red[8];

    float m = -1e30f;
    for (int i = tid * 4; i < VOCAB; i += 1024) {
        const float4 v = *(const float4*)&row[i];
        m = fmaxf(m, fmaxf(fmaxf(v.x, v.y), fmaxf(v.z, v.w)));
    }
    #pragma unroll
    for (int o = 16; o; o >>= 1) m = fmaxf(m, __shfl_xor_sync(0xffffffffu, m, o));
    if ((tid & 31) == 0) red[tid >> 5] = m;
    __syncthreads();
    float M = red[0];
    #pragma unroll
    for (int j = 1; j < 8; ++j) M = fmaxf(M, red[j]);
    __syncthreads();

    float s = 0.f;
    for (int i = tid * 4; i < VOCAB; i += 1024) {
        const float4 v = *(const float4*)&row[i];
        s += expf(v.x - M) + expf(v.y - M) + expf(v.z - M) + expf(v.w - M);
    }
    #pragma unroll
    for (int o = 16; o; o >>= 1) s += __shfl_xor_sync(0xffffffffu, s, o);
    if ((tid & 31) == 0) red[tid >> 5] = s;
    __syncthreads();
    float S = 0.f;
    #pragma unroll
    for (int j = 0; j < 8; ++j) S += red[j];
    const float lse = M + logf(S);

    for (int i = tid * 4; i < VOCAB; i += 1024) {
        float4 v = *(const float4*)&row[i];
        v.x -= lse; v.y -= lse; v.z -= lse; v.w -= lse;
        *(float4*)&row[i] = v;
    }
}

// ---------------------------------------------------------------------------
// kernel_launch — 3 graph nodes total
// Inputs: 0 hidden [B,1,D] | 1 tokens [B,T] int | 2 emb_out [V,D] | 3 W_dt [2D,D]
//         4 b_dt [D] | 5 gamma [D] | 6 beta [D] | 7 W_v [D,V] | 8 b_v [V]
// Output: [ z (B*D) | y (B*V) ] f32
// ---------------------------------------------------------------------------
extern "C" void kernel_launch(void* const* d_in, const int* in_sizes, int n_in,
                              void* d_out, int out_size)
{
    const float* hidden = (const float*)d_in[0];
    const int*   tok    = (const int*)  d_in[1];
    const float* emb    = (const float*)d_in[2];
    const float* Wdt    = (const float*)d_in[3];
    const float* bdt    = (const float*)d_in[4];
    const float* gamma  = (const float*)d_in[5];
    const float* beta   = (const float*)d_in[6];
    const float* Wv     = (const float*)d_in[7];
    const float* bv     = (const float*)d_in[8];

    float* zout = (float*)d_out;
    float* yout = zout + (size_t)BATCH * DIM;

    rnn_persistent<<<NCTA, 256>>>(hidden, tok, emb, Wdt, bdt, gamma, beta, zout);
    logits_kernel<<<dim3(VOCAB / VT, BATCH / BT), 256>>>(zout, Wv, bv, yout);
    logsoftmax_kernel<<<BATCH, 256>>>(yout);
}

// round 5
// speedup vs baseline: 1.0490x; 1.0013x over previous
#include <cuda_runtime.h>
#include <math.h>

// Problem constants
#define BATCH 256
#define TLEN  512
#define DIM   1024
#define VOCAB 32000

// Step-GEMM tiling inside the persistent kernel:
// grid = 256 CTAs; CTA bid -> GEMM tile (kc = bid>>5, nc = bid&31), LN row b = bid
#define NK 8
#define NN 32
#define KT (DIM / NK)   // 128
#define NT (DIM / NN)   // 32
#define NCTA 256

// Logits tiling
#define VT 128
#define BT 32

// ---------------------------------------------------------------------------
// Device scratch (static — no cudaMalloc allowed)
// ---------------------------------------------------------------------------
__device__ float g_P[NK][BATCH][DIM];   // 8 MB partial sums (lives in L2)
__device__ float g_UT[DIM][BATCH];      // current u, transposed (K-major)
__device__ float g_HT[DIM][BATCH];      // transposed hidden_state
__device__ unsigned g_bar_arrive = 0;
__device__ unsigned g_bar_gen    = 0;

// ---------------------------------------------------------------------------
// Packed f32x2 helpers (Blackwell FFMA2 — only reachable via PTX)
// ---------------------------------------------------------------------------
__device__ __forceinline__ unsigned long long pack2(float lo, float hi)
{
    unsigned long long r;
    asm("mov.b64 %0, {%1, %2};" : "=l"(r) : "f"(lo), "f"(hi));
    return r;
}
__device__ __forceinline__ float2 unpack2(unsigned long long v)
{
    float2 r;
    asm("mov.b64 {%0, %1}, %2;" : "=f"(r.x), "=f"(r.y) : "l"(v));
    return r;
}
__device__ __forceinline__ void ffma2(unsigned long long& acc,
                                      unsigned long long a,
                                      unsigned long long b)
{
    asm("fma.rn.f32x2 %0, %1, %2, %0;" : "+l"(acc) : "l"(a), "l"(b));
}

// ---------------------------------------------------------------------------
// Grid-wide barrier (sense-reversing, all 256 CTAs co-resident by construction)
// ---------------------------------------------------------------------------
__device__ __forceinline__ void grid_barrier()
{
    __threadfence();
    __syncthreads();
    if (threadIdx.x == 0) {
        unsigned gen = *(volatile unsigned*)&g_bar_gen;
        if (atomicAdd(&g_bar_arrive, 1u) == NCTA - 1u) {
            atomicExch(&g_bar_arrive, 0u);
            __threadfence();
            atomicAdd(&g_bar_gen, 1u);     // release
        } else {
            while (*(volatile unsigned*)&g_bar_gen == gen) { }
        }
        __threadfence();
    }
    __syncthreads();
}

// ---------------------------------------------------------------------------
// One GEMM tile: P[kc][b][n0..n0+31] = sum over K-tile [k0, k0+128)
// src is [DIM][BATCH] (K-major), W tile already resident in sW.
// FFMA2 inner loop: batch pairs packed in f32x2 lanes.
// ---------------------------------------------------------------------------
__device__ __forceinline__ void gemm_tile(
    const float* __restrict__ src,
    float (&sW)[KT][NT], float (&sU)[16][BATCH],
    int k0, int n0, int kc, int tid)
{
    const int nb = tid & 15;          // n-pair: n0 + 2*nb, +1
    const int bg = tid >> 4;          // b-group: b = bg*16 .. +15
    const int pr = tid >> 6;          // prefetch row base (0..3)
    const int pc = (tid * 4) & 255;   // prefetch col (float4)

    unsigned long long ax[8], ay[8];
    #pragma unroll
    for (int j = 0; j < 8; ++j) { ax[j] = 0ull; ay[j] = 0ull; }

    // prefetch slab 0
    float4 pf[4];
    #pragma unroll
    for (int i = 0; i < 4; ++i)
        pf[i] = __ldcg((const float4*)&src[(size_t)(k0 + pr + i * 4) * BATCH + pc]);

    for (int slab = 0; slab < KT / 16; ++slab) {
        __syncthreads();
        #pragma unroll
        for (int i = 0; i < 4; ++i)
            *(float4*)&sU[pr + i * 4][pc] = pf[i];
        __syncthreads();

        // issue next slab's loads early — latency hides under compute
        if (slab + 1 < KT / 16) {
            #pragma unroll
            for (int i = 0; i < 4; ++i)
                pf[i] = __ldcg((const float4*)&src[
                    (size_t)(k0 + (slab + 1) * 16 + pr + i * 4) * BATCH + pc]);
        }

        #pragma unroll
        for (int kk = 0; kk < 16; ++kk) {
            const float2 w = *(const float2*)&sW[slab * 16 + kk][nb * 2];
            const unsigned long long wxx = pack2(w.x, w.x);
            const unsigned long long wyy = pack2(w.y, w.y);
            const ulonglong2* up = (const ulonglong2*)&sU[kk][bg * 16];
            #pragma unroll
            for (int q = 0; q < 4; ++q) {
                const ulonglong2 u = up[q];
                ffma2(ax[q * 2 + 0], u.x, wxx);
                ffma2(ay[q * 2 + 0], u.x, wyy);
                ffma2(ax[q * 2 + 1], u.y, wxx);
                ffma2(ay[q * 2 + 1], u.y, wyy);
            }
        }
    }

    #pragma unroll
    for (int j = 0; j < 8; ++j) {
        const float2 x = unpack2(ax[j]);   // batches (2j, 2j+1), col even
        const float2 y = unpack2(ay[j]);   // batches (2j, 2j+1), col odd
        __stcg((float2*)&g_P[kc][bg * 16 + 2 * j + 0][n0 + nb * 2],
               make_float2(x.x, y.x));
        __stcg((float2*)&g_P[kc][bg * 16 + 2 * j + 1][n0 + nb * 2],
               make_float2(x.y, y.y));
    }
}

// ---------------------------------------------------------------------------
// Persistent scan kernel: init + c-precompute + 512 steps of (GEMM, LN)
// ---------------------------------------------------------------------------
__global__ __launch_bounds__(256, 2) void rnn_persistent(
    const float* __restrict__ hidden, const int* __restrict__ tok,
    const float* __restrict__ emb,    const float* __restrict__ Wdt,
    const float* __restrict__ bdt,    const float* __restrict__ gamma,
    const float* __restrict__ beta,   float* __restrict__ zout)
{
    __shared__ float sW[KT][NT];     // 16 KB — W tile (persistent across steps)
    __shared__ float sU[16][BATCH];  // 16 KB — activation slab
    __shared__ float red[2][8];

    const int tid = threadIdx.x;
    const int bid = blockIdx.x;
    const int nc  = bid & 31,  kc = bid >> 5;
    const int n0  = nc * NT,   k0 = kc * KT;
    const int b   = bid;          // LN role: batch row
    const int d0  = tid * 4;      // LN role: this thread's 4 channels

    // ---- init: transpose hidden into g_HT; u0 = emb[token[:,0]] into g_UT ----
    {
        #pragma unroll
        for (int i = 0; i < 4; ++i) {
            int d = tid + i * 256;
            g_HT[d][b] = hidden[(size_t)b * DIM + d];
        }
        const int tk0 = tok[(size_t)b * TLEN];
        #pragma unroll
        for (int i = 0; i < 4; ++i) {
            int d = tid + i * 256;
            g_UT[d][b] = emb[(size_t)tk0 * DIM + d];
        }
    }

    // u row for this CTA's batch row (registers, persistent over the scan)
    float4 ureg;
    {
        const int tk0 = tok[(size_t)b * TLEN];
        ureg = *(const float4*)&emb[(size_t)tk0 * DIM + d0];
    }
    const float4 g4 = *(const float4*)&gamma[d0];
    const float4 b4 = *(const float4*)&beta[d0];

    // ---- c = hidden @ W_bot + b_dt (precompute; W_bot = rows D..2D-1) ----
    #pragma unroll
    for (int idx = tid; idx < KT * NT; idx += 256) {
        int k = idx >> 5, n = idx & 31;
        sW[k][n] = Wdt[(size_t)(DIM + k0 + k) * DIM + n0 + n];
    }
    grid_barrier();                    // g_HT complete everywhere
    gemm_tile(&g_HT[0][0], sW, sU, k0, n0, kc, tid);
    grid_barrier();                    // g_P complete

    float4 creg = *(const float4*)&bdt[d0];
    #pragma unroll
    for (int j = 0; j < NK; ++j) {
        float4 p = __ldcg((const float4*)&g_P[j][b][d0]);
        creg.x += p.x; creg.y += p.y; creg.z += p.z; creg.w += p.w;
    }

    // load W_top tile (persistent for all 512 steps)
    __syncthreads();
    #pragma unroll
    for (int idx = tid; idx < KT * NT; idx += 256) {
        int k = idx >> 5, n = idx & 31;
        sW[k][n] = Wdt[(size_t)(k0 + k) * DIM + n0 + n];
    }
    grid_barrier();                    // everyone done reading P before loop overwrites

    // ---- scan ----
    for (int t = 0; t < TLEN; ++t) {
        gemm_tile(&g_UT[0][0], sW, sU, k0, n0, kc, tid);
        grid_barrier();

        // LN role: y = C + U + sum_j P[j]
        float4 y = creg;
        y.x += ureg.x; y.y += ureg.y; y.z += ureg.z; y.w += ureg.w;
        #pragma unroll
        for (int j = 0; j < NK; ++j) {
            float4 p = __ldcg((const float4*)&g_P[j][b][d0]);
            y.x += p.x; y.y += p.y; y.z += p.z; y.w += p.w;
        }

        float s1 = y.x + y.y + y.z + y.w;
        float s2 = y.x*y.x + y.y*y.y + y.z*y.z + y.w*y.w;
        #pragma unroll
        for (int o = 16; o; o >>= 1) {
            s1 += __shfl_xor_sync(0xffffffffu, s1, o);
            s2 += __shfl_xor_sync(0xffffffffu, s2, o);
        }
        if ((tid & 31) == 0) { red[0][tid >> 5] = s1; red[1][tid >> 5] = s2; }
        __syncthreads();
        float t1 = 0.f, t2 = 0.f;
        #pragma unroll
        for (int j = 0; j < 8; ++j) { t1 += red[0][j]; t2 += red[1][j]; }
        __syncthreads();

        const float mean = t1 * (1.f / DIM);
        const float var  = t2 * (1.f / DIM) - mean * mean;
        const float rstd = rsqrtf(var + 1e-5f);

        float4 s;
        s.x = (y.x - mean) * rstd * g4.x + b4.x;
        s.y = (y.y - mean) * rstd * g4.y + b4.y;
        s.z = (y.z - mean) * rstd * g4.z + b4.z;
        s.w = (y.w - mean) * rstd * g4.w + b4.w;

        if (t < TLEN - 1) {
            const int tk = tok[(size_t)b * TLEN + t + 1];
            const float4 e = *(const float4*)&emb[(size_t)tk * DIM + d0];
            ureg.x = s.x + e.x; ureg.y = s.y + e.y;
            ureg.z = s.z + e.z; ureg.w = s.w + e.w;
            __stcg(&g_UT[d0 + 0][b], ureg.x);
            __stcg(&g_UT[d0 + 1][b], ureg.y);
            __stcg(&g_UT[d0 + 2][b], ureg.z);
            __stcg(&g_UT[d0 + 3][b], ureg.w);
        } else {
            *(float4*)&zout[(size_t)b * DIM + d0] = s;
        }
        grid_barrier();
    }
}

// ---------------------------------------------------------------------------
// Logits: L[b][v] = sum_d z[b][d] * Wv[d][v] + bv[v]   (FFMA2 over v-pairs)
// ---------------------------------------------------------------------------
__global__ __launch_bounds__(256, 2) void logits_kernel(
    const float* __restrict__ z, const float* __restrict__ Wv,
    const float* __restrict__ bv, float* __restrict__ L)
{
    __shared__ float sS[BT][64];     // 8 KB
    __shared__ float sWv[64][VT];    // 32 KB

    const int tid = threadIdx.x;
    const int v0  = blockIdx.x * VT;
    const int b0  = blockIdx.y * BT;
    const int vb  = tid & 31;
    const int bg  = tid >> 5;

    unsigned long long acc[4][2];
    #pragma unroll
    for (int i = 0; i < 4; ++i) { acc[i][0] = 0ull; acc[i][1] = 0ull; }

    for (int slab = 0; slab < DIM / 64; ++slab) {
        const int d0 = slab * 64;
        __syncthreads();
        for (int idx = tid; idx < BT * 64; idx += 256)
            sS[idx >> 6][idx & 63] = z[(size_t)(b0 + (idx >> 6)) * DIM + d0 + (idx & 63)];
        for (int idx = tid; idx < 64 * VT; idx += 256)
            sWv[idx >> 7][idx & 127] = Wv[(size_t)(d0 + (idx >> 7)) * VOCAB + v0 + (idx & 127)];
        __syncthreads();

        #pragma unroll 4
        for (int d = 0; d < 64; ++d) {
            const ulonglong2 w2 = *(const ulonglong2*)&sWv[d][vb * 4];
            #pragma unroll
            for (int i = 0; i < 4; ++i) {
                const float u = sS[bg * 4 + i][d];
                const unsigned long long uu = pack2(u, u);
                ffma2(acc[i][0], uu, w2.x);
                ffma2(acc[i][1], uu, w2.y);
            }
        }
    }

    const float4 bvv = *(const float4*)&bv[v0 + vb * 4];
    #pragma unroll
    for (int i = 0; i < 4; ++i) {
        const float2 p0 = unpack2(acc[i][0]);
        const float2 p1 = unpack2(acc[i][1]);
        float4 r = make_float4(p0.x + bvv.x, p0.y + bvv.y,
                               p1.x + bvv.z, p1.y + bvv.w);
        *(float4*)&L[(size_t)(b0 + bg * 4 + i) * VOCAB + v0 + vb * 4] = r;
    }
}

// ---------------------------------------------------------------------------
// In-place log_softmax over each row of L [BATCH][VOCAB]
// ---------------------------------------------------------------------------
__global__ __launch_bounds__(256) void logsoftmax_kernel(float* __restrict__ L)
{
    const int b   = blockIdx.x;
    const int tid = threadIdx.x;
    float* row = L + (size_t)b * VOCAB;
    __shared__ float red[8];

    float m = -1e30f;
    for (int i = tid * 4; i < VOCAB; i += 1024) {
        const float4 v = *(const float4*)&row[i];
        m = fmaxf(m, fmaxf(fmaxf(v.x, v.y), fmaxf(v.z, v.w)));
    }
    #pragma unroll
    for (int o = 16; o; o >>= 1) m = fmaxf(m, __shfl_xor_sync(0xffffffffu, m, o));
    if ((tid & 31) == 0) red[tid >> 5] = m;
    __syncthreads();
    float M = red[0];
    #pragma unroll
    for (int j = 1; j < 8; ++j) M = fmaxf(M, red[j]);
    __syncthreads();

    float s = 0.f;
    for (int i = tid * 4; i < VOCAB; i += 1024) {
        const float4 v = *(const float4*)&row[i];
        s += expf(v.x - M) + expf(v.y - M) + expf(v.z - M) + expf(v.w - M);
    }
    #pragma unroll
    for (int o = 16; o; o >>= 1) s += __shfl_xor_sync(0xffffffffu, s, o);
    if ((tid & 31) == 0) red[tid >> 5] = s;
    __syncthreads();
    float S = 0.f;
    #pragma unroll
    for (int j = 0; j < 8; ++j) S += red[j];
    const float lse = M + logf(S);

    for (int i = tid * 4; i < VOCAB; i += 1024) {
        float4 v = *(const float4*)&row[i];
        v.x -= lse; v.y -= lse; v.z -= lse; v.w -= lse;
        *(float4*)&row[i] = v;
    }
}

// ---------------------------------------------------------------------------
// kernel_launch — 3 graph nodes total
// Inputs: 0 hidden [B,1,D] | 1 tokens [B,T] int | 2 emb_out [V,D] | 3 W_dt [2D,D]
//         4 b_dt [D] | 5 gamma [D] | 6 beta [D] | 7 W_v [D,V] | 8 b_v [V]
// Output: [ z (B*D) | y (B*V) ] f32
// ---------------------------------------------------------------------------
extern "C" void kernel_launch(void* const* d_in, const int* in_sizes, int n_in,
                              void* d_out, int out_size)
{
    const float* hidden = (const float*)d_in[0];
    const int*   tok    = (const int*)  d_in[1];
    const float* emb    = (const float*)d_in[2];
    const float* Wdt    = (const float*)d_in[3];
    const float* bdt    = (const float*)d_in[4];
    const float* gamma  = (const float*)d_in[5];
    const float* beta   = (const float*)d_in[6];
    const float* Wv     = (const float*)d_in[7];
    const float* bv     = (const float*)d_in[8];

    float* zout = (float*)d_out;
    float* yout = zout + (size_t)BATCH * DIM;

    rnn_persistent<<<NCTA, 256>>>(hidden, tok, emb, Wdt, bdt, gamma, beta, zout);
    logits_kernel<<<dim3(VOCAB / VT, BATCH / BT), 256>>>(zout, Wv, bv, yout);
    logsoftmax_kernel<<<BATCH, 256>>>(yout);
}

// round 8
// speedup vs baseline: 1.2445x; 1.1864x over previous
#include <cuda_runtime.h>
#include <cuda_bf16.h>
#include <math.h>
#include <stdint.h>

// Problem constants
#define BATCH 256
#define TLEN  512
#define DIM   1024
#define VOCAB 32000

// Persistent tiling: 256 CTAs; CTA bid -> (kc = bid>>5 of 8, nc = bid&31 of 32)
//   GEMM tile: 256 batch rows x 32 cols x 128 K. LN row b = bid.
#define NK 8
#define NN 32
#define KT 128
#define NT 32
#define NCTA 256
#define CK 32                 // K-chunk rows per cp.async stage

// Logits tiling
#define VT 128
#define BT 32

// SMEM layout (dynamic):
//  sW: [2 splits][128 k][40 bf16]  stride 80B  -> 2 x 10240 = 20480 B
//  sA: [2 bufs][2 splits][32 k][264 bf16] stride 528B -> per split 16896 B
#define SM_W    0
#define W_SPL   10240u
#define SM_A    20480
#define ASPL    16896u        // per-split chunk bytes (32 rows x 528)
#define ABUF    33792u        // per-buf (2 splits)
#define ASTRIDE 528u
#define SMEM_BYTES (20480 + 2 * 33792)   // 88064

// ---------------------------------------------------------------------------
// Device scratch (static — no cudaMalloc allowed)
// ---------------------------------------------------------------------------
__device__ __nv_bfloat16 g_Wbf[2][2][DIM][DIM];   // [half][hi/lo][k][n]
__device__ float         g_P[NK][BATCH][DIM];     // partial sums
__device__ __nv_bfloat16 g_UThi[DIM][BATCH], g_UTlo[DIM][BATCH];  // u^T, split
__device__ __nv_bfloat16 g_HThi[DIM][BATCH], g_HTlo[DIM][BATCH];  // hidden^T, split
__device__ unsigned g_bar_arrive = 0;
__device__ unsigned g_bar_gen    = 0;

// ---------------------------------------------------------------------------
// PTX helpers
// ---------------------------------------------------------------------------
__device__ __forceinline__ uint32_t smem_u32(const void* p) {
    uint32_t a;
    asm("{ .reg .u64 t; cvta.to.shared.u64 t, %1; cvt.u32.u64 %0, t; }" : "=r"(a) : "l"(p));
    return a;
}
__device__ __forceinline__ void cp_async16(uint32_t dst, const void* src) {
    asm volatile("cp.async.cg.shared.global [%0], [%1], 16;" :: "r"(dst), "l"(src) : "memory");
}
#define CP_COMMIT() asm volatile("cp.async.commit_group;" ::: "memory")
#define CP_WAIT(n)  asm volatile("cp.async.wait_group %0;" :: "n"(n) : "memory")

__device__ __forceinline__ void ldm_x4_t(uint32_t* r, uint32_t addr) {
    asm volatile("ldmatrix.sync.aligned.m8n8.x4.trans.shared.b16 {%0,%1,%2,%3}, [%4];"
                 : "=r"(r[0]), "=r"(r[1]), "=r"(r[2]), "=r"(r[3]) : "r"(addr));
}
__device__ __forceinline__ void ldm_x2_t(uint32_t* r, uint32_t addr) {
    asm volatile("ldmatrix.sync.aligned.m8n8.x2.trans.shared.b16 {%0,%1}, [%2];"
                 : "=r"(r[0]), "=r"(r[1]) : "r"(addr));
}
__device__ __forceinline__ void mma_bf16(float* c, const uint32_t* a, const uint32_t* b) {
    asm volatile(
        "mma.sync.aligned.m16n8k16.row.col.f32.bf16.bf16.f32 "
        "{%0,%1,%2,%3}, {%4,%5,%6,%7}, {%8,%9}, {%0,%1,%2,%3};"
        : "+f"(c[0]), "+f"(c[1]), "+f"(c[2]), "+f"(c[3])
        : "r"(a[0]), "r"(a[1]), "r"(a[2]), "r"(a[3]), "r"(b[0]), "r"(b[1]));
}
__device__ __forceinline__ void st_bf16_cg(__nv_bfloat16* p, __nv_bfloat16 v) {
    unsigned short u = __bfloat16_as_ushort(v);
    asm volatile("st.global.cg.u16 [%0], %1;" :: "l"(p), "h"(u) : "memory");
}

// ---------------------------------------------------------------------------
// Grid-wide barrier (sense-reversing; 256 CTAs, 2/SM co-resident)
// ---------------------------------------------------------------------------
__device__ __forceinline__ void grid_barrier()
{
    __threadfence();
    __syncthreads();
    if (threadIdx.x == 0) {
        unsigned gen = *(volatile unsigned*)&g_bar_gen;
        if (atomicAdd(&g_bar_arrive, 1u) == NCTA - 1u) {
            atomicExch(&g_bar_arrive, 0u);
            __threadfence();
            atomicAdd(&g_bar_gen, 1u);
        } else {
            while (*(volatile unsigned*)&g_bar_gen == gen) { }
        }
        __threadfence();
    }
    __syncthreads();
}

// ---------------------------------------------------------------------------
// W prep: Wdt [2D][D] fp32 -> g_Wbf[half][hi/lo][k][n] bf16
// ---------------------------------------------------------------------------
__global__ void prep_w(const float* __restrict__ Wdt)
{
    const int i = blockIdx.x * 256 + threadIdx.x;   // 0 .. 2*D*D-1
    const int kk = i >> 10;
    const int n  = i & 1023;
    const int half = kk >> 10;
    const int k  = kk & 1023;
    const float v = Wdt[(size_t)kk * DIM + n];
    const __nv_bfloat16 hi = __float2bfloat16(v);
    const __nv_bfloat16 lo = __float2bfloat16(v - __bfloat162float(hi));
    g_Wbf[half][0][k][n] = hi;
    g_Wbf[half][1][k][n] = lo;
}

// ---------------------------------------------------------------------------
// In-kernel loaders
// ---------------------------------------------------------------------------
__device__ __forceinline__ void load_w(char* smp, int half, int k0, int n0, int tid)
{
    #pragma unroll
    for (int t = 0; t < 16; ++t) {
        const int i  = tid + t * 256;     // 0..4095
        const int sp = i >> 11;
        const int k  = (i >> 4) & 127;
        const int n2 = i & 15;            // pair of n
        const uint32_t v = *(const uint32_t*)&g_Wbf[half][sp][k0 + k][n0 + n2 * 2];
        *(uint32_t*)(smp + SM_W + sp * W_SPL + (uint32_t)k * 80u + (uint32_t)n2 * 4u) = v;
    }
}

// cp.async one 32-k chunk of A^T (hi+lo): 32 rows x 512B x 2 splits = 2048 x 16B
__device__ __forceinline__ void issue_chunk(uint32_t sa_base,
    const __nv_bfloat16* __restrict__ srchi, const __nv_bfloat16* __restrict__ srclo,
    int kglob, int tid)
{
    #pragma unroll
    for (int t = 0; t < 8; ++t) {
        const int i  = tid + t * 256;     // 0..2047
        const int sp = i >> 10;
        const int r  = (i >> 5) & 31;
        const int c  = i & 31;            // 16B column (8 bf16)
        const __nv_bfloat16* src = (sp ? srclo : srchi) + (size_t)(kglob + r) * BATCH + c * 8;
        const uint32_t dst = sa_base + (uint32_t)sp * ASPL + (uint32_t)r * ASTRIDE + (uint32_t)c * 16u;
        cp_async16(dst, src);
    }
    CP_COMMIT();
}

// ---------------------------------------------------------------------------
// Compute one 32-k chunk: 2 ksteps x (2 m-tiles x 4 n-tiles x 3 split products)
// A^T in smem [k][m] stride 528B; W in smem [k][n] stride 80B.
// ---------------------------------------------------------------------------
__device__ __forceinline__ void compute_chunk(uint32_t abase, uint32_t wbase, int kb,
                                              float acc[2][4][4], int lane, int wid)
{
    #pragma unroll
    for (int ks = 0; ks < 2; ++ks) {
        // B fragments: trans-ldmatrix from W [k][n]; lanes 0-15 give k rows
        uint32_t bh[4][2], bl[4][2];
        const uint32_t krow_b = (uint32_t)(kb + ks * 16 + (lane & 15));
        #pragma unroll
        for (int nt = 0; nt < 4; ++nt) {
            ldm_x2_t(bh[nt], wbase + 0u    + krow_b * 80u + (uint32_t)nt * 16u);
            ldm_x2_t(bl[nt], wbase + W_SPL + krow_b * 80u + (uint32_t)nt * 16u);
        }
        // A fragments: trans-ldmatrix from A^T [k][m] (rows within chunk 0..31)
        const int g = lane >> 3;
        const uint32_t arow  = (uint32_t)(ks * 16 + (g >> 1) * 8 + (lane & 7));
        const uint32_t amcol = (uint32_t)(wid * 32 + (g & 1) * 8) * 2u;
        uint32_t ah[2][4], al[2][4];
        #pragma unroll
        for (int mt = 0; mt < 2; ++mt) {
            const uint32_t off = arow * ASTRIDE + amcol + (uint32_t)mt * 32u;
            ldm_x4_t(ah[mt], abase + off);
            ldm_x4_t(al[mt], abase + ASPL + off);
        }
        #pragma unroll
        for (int mt = 0; mt < 2; ++mt)
            #pragma unroll
            for (int nt = 0; nt < 4; ++nt) {
                mma_bf16(acc[mt][nt], ah[mt], bh[nt]);
                mma_bf16(acc[mt][nt], ah[mt], bl[nt]);
                mma_bf16(acc[mt][nt], al[mt], bh[nt]);
            }
    }
}

// ---------------------------------------------------------------------------
// One full step GEMM: P[kc][all 256 b][n0..n0+31] over K [k0, k0+128)
// 4 chunks of K=32, double-buffered cp.async pipeline.
// ---------------------------------------------------------------------------
__device__ __forceinline__ void gemm_step_mma(char* smp, uint32_t base,
    const __nv_bfloat16* __restrict__ srchi, const __nv_bfloat16* __restrict__ srclo,
    int k0, int n0, int kc, int tid)
{
    const int lane = tid & 31, wid = tid >> 5;
    float acc[2][4][4];
    #pragma unroll
    for (int mt = 0; mt < 2; ++mt)
        #pragma unroll
        for (int nt = 0; nt < 4; ++nt)
            #pragma unroll
            for (int q = 0; q < 4; ++q) acc[mt][nt][q] = 0.f;

    const uint32_t a0 = base + SM_A;
    const uint32_t a1 = base + SM_A + ABUF;
    const uint32_t wb = base + SM_W;

    issue_chunk(a0, srchi, srclo, k0 + 0 * CK, tid);
    issue_chunk(a1, srchi, srclo, k0 + 1 * CK, tid);

    CP_WAIT(1); __syncthreads();
    compute_chunk(a0, wb, 0 * CK, acc, lane, wid);
    __syncthreads();
    issue_chunk(a0, srchi, srclo, k0 + 2 * CK, tid);

    CP_WAIT(1); __syncthreads();
    compute_chunk(a1, wb, 1 * CK, acc, lane, wid);
    __syncthreads();
    issue_chunk(a1, srchi, srclo, k0 + 3 * CK, tid);

    CP_WAIT(1); __syncthreads();
    compute_chunk(a0, wb, 2 * CK, acc, lane, wid);

    CP_WAIT(0); __syncthreads();
    compute_chunk(a1, wb, 3 * CK, acc, lane, wid);

    // store accumulators -> g_P[kc] (warp wid owns rows wid*32..+31)
    const int r4 = lane >> 2, c2 = (lane & 3) * 2;
    #pragma unroll
    for (int mt = 0; mt < 2; ++mt)
        #pragma unroll
        for (int nt = 0; nt < 4; ++nt) {
            const int r0 = wid * 32 + mt * 16 + r4;
            const int cc = n0 + nt * 8 + c2;
            __stcg((float2*)&g_P[kc][r0][cc],     make_float2(acc[mt][nt][0], acc[mt][nt][1]));
            __stcg((float2*)&g_P[kc][r0 + 8][cc], make_float2(acc[mt][nt][2], acc[mt][nt][3]));
        }
}

// ---------------------------------------------------------------------------
// Persistent scan kernel: init + c precompute + 512 x (HMMA GEMM, LN)
// ---------------------------------------------------------------------------
__global__ __launch_bounds__(256, 2) void rnn_persistent(
    const float* __restrict__ hidden, const int* __restrict__ tok,
    const float* __restrict__ emb,    const float* __restrict__ bdt,
    const float* __restrict__ gamma,  const float* __restrict__ beta,
    float* __restrict__ zout)
{
    extern __shared__ char smp[];
    const uint32_t base = smem_u32(smp);
    __shared__ float red[2][8];

    const int tid = threadIdx.x;
    const int bid = blockIdx.x;
    const int nc = bid & 31, kc = bid >> 5;
    const int n0 = nc * NT,  k0 = kc * KT;
    const int b  = bid;           // LN row
    const int d0 = tid * 4;       // LN channels

    // ---- init: transposed bf16 splits of hidden and u0 ----
    {
        const int tk0 = tok[(size_t)b * TLEN];
        #pragma unroll
        for (int j = 0; j < 4; ++j) {
            const int d = tid + j * 256;
            const float hv = hidden[(size_t)b * DIM + d];
            const float uv = emb[(size_t)tk0 * DIM + d];
            __nv_bfloat16 hh = __float2bfloat16(hv);
            __nv_bfloat16 hl = __float2bfloat16(hv - __bfloat162float(hh));
            __nv_bfloat16 uh = __float2bfloat16(uv);
            __nv_bfloat16 ul = __float2bfloat16(uv - __bfloat162float(uh));
            st_bf16_cg(&g_HThi[d][b], hh);
            st_bf16_cg(&g_HTlo[d][b], hl);
            st_bf16_cg(&g_UThi[d][b], uh);
            st_bf16_cg(&g_UTlo[d][b], ul);
        }
    }

    // u row in fp32 registers (exact residual path)
    float4 ureg;
    {
        const int tk0 = tok[(size_t)b * TLEN];
        ureg = *(const float4*)&emb[(size_t)tk0 * DIM + d0];
    }
    const float4 g4 = *(const float4*)&gamma[d0];
    const float4 b4 = *(const float4*)&beta[d0];

    // ---- c = hidden @ W_bot + b_dt ----
    load_w(smp, 1, k0, n0, tid);
    grid_barrier();                     // H/U transposed splits visible everywhere
    gemm_step_mma(smp, base, &g_HThi[0][0], &g_HTlo[0][0], k0, n0, kc, tid);
    grid_barrier();                     // g_P complete

    float4 creg = *(const float4*)&bdt[d0];
    #pragma unroll
    for (int j = 0; j < NK; ++j) {
        const float4 p = __ldcg((const float4*)&g_P[j][b][d0]);
        creg.x += p.x; creg.y += p.y; creg.z += p.z; creg.w += p.w;
    }

    __syncthreads();
    load_w(smp, 0, k0, n0, tid);        // W_top, persistent for the scan
    grid_barrier();                     // P consumed before step 0 overwrites

    // ---- scan ----
    for (int t = 0; t < TLEN; ++t) {
        gemm_step_mma(smp, base, &g_UThi[0][0], &g_UTlo[0][0], k0, n0, kc, tid);
        grid_barrier();

        // LN: y = C + U + sum_j P[j]
        float4 y = creg;
        y.x += ureg.x; y.y += ureg.y; y.z += ureg.z; y.w += ureg.w;
        #pragma unroll
        for (int j = 0; j < NK; ++j) {
            const float4 p = __ldcg((const float4*)&g_P[j][b][d0]);
            y.x += p.x; y.y += p.y; y.z += p.z; y.w += p.w;
        }

        float s1 = y.x + y.y + y.z + y.w;
        float s2 = y.x*y.x + y.y*y.y + y.z*y.z + y.w*y.w;
        #pragma unroll
        for (int o = 16; o; o >>= 1) {
            s1 += __shfl_xor_sync(0xffffffffu, s1, o);
            s2 += __shfl_xor_sync(0xffffffffu, s2, o);
        }
        if ((tid & 31) == 0) { red[0][tid >> 5] = s1; red[1][tid >> 5] = s2; }
        __syncthreads();
        float t1 = 0.f, t2 = 0.f;
        #pragma unroll
        for (int j = 0; j < 8; ++j) { t1 += red[0][j]; t2 += red[1][j]; }
        __syncthreads();

        const float mean = t1 * (1.f / DIM);
        const float var  = t2 * (1.f / DIM) - mean * mean;
        const float rstd = rsqrtf(var + 1e-5f);

        float4 s;
        s.x = (y.x - mean) * rstd * g4.x + b4.x;
        s.y = (y.y - mean) * rstd * g4.y + b4.y;
        s.z = (y.z - mean) * rstd * g4.z + b4.z;
        s.w = (y.w - mean) * rstd * g4.w + b4.w;

        if (t < TLEN - 1) {
            const int tk = tok[(size_t)b * TLEN + t + 1];
            const float4 e = *(const float4*)&emb[(size_t)tk * DIM + d0];
            float un[4] = { s.x + e.x, s.y + e.y, s.z + e.z, s.w + e.w };
            ureg.x = un[0]; ureg.y = un[1]; ureg.z = un[2]; ureg.w = un[3];
            #pragma unroll
            for (int i = 0; i < 4; ++i) {
                const __nv_bfloat16 uh = __float2bfloat16(un[i]);
                const __nv_bfloat16 ul = __float2bfloat16(un[i] - __bfloat162float(uh));
                st_bf16_cg(&g_UThi[d0 + i][b], uh);
                st_bf16_cg(&g_UTlo[d0 + i][b], ul);
            }
        } else {
            *(float4*)&zout[(size_t)b * DIM + d0] = s;
        }
        grid_barrier();
    }
}

// ---------------------------------------------------------------------------
// Packed f32x2 helpers (logits kernel)
// ---------------------------------------------------------------------------
__device__ __forceinline__ unsigned long long pack2(float lo, float hi)
{
    unsigned long long r;
    asm("mov.b64 %0, {%1, %2};" : "=l"(r) : "f"(lo), "f"(hi));
    return r;
}
__device__ __forceinline__ float2 unpack2(unsigned long long v)
{
    float2 r;
    asm("mov.b64 {%0, %1}, %2;" : "=f"(r.x), "=f"(r.y) : "l"(v));
    return r;
}
__device__ __forceinline__ void ffma2(unsigned long long& acc,
                                      unsigned long long a, unsigned long long b)
{
    asm("fma.rn.f32x2 %0, %1, %2, %0;" : "+l"(acc) : "l"(a), "l"(b));
}

// ---------------------------------------------------------------------------
// Logits: L[b][v] = sum_d z[b][d] * Wv[d][v] + bv[v]
// ---------------------------------------------------------------------------
__global__ __launch_bounds__(256, 2) void logits_kernel(
    const float* __restrict__ z, const float* __restrict__ Wv,
    const float* __restrict__ bv, float* __restrict__ L)
{
    __shared__ float sS[BT][64];
    __shared__ float sWv[64][VT];

    const int tid = threadIdx.x;
    const int v0  = blockIdx.x * VT;
    const int b0  = blockIdx.y * BT;
    const int vb  = tid & 31;
    const int bg  = tid >> 5;

    unsigned long long acc[4][2];
    #pragma unroll
    for (int i = 0; i < 4; ++i) { acc[i][0] = 0ull; acc[i][1] = 0ull; }

    for (int slab = 0; slab < DIM / 64; ++slab) {
        const int d0 = slab * 64;
        __syncthreads();
        for (int idx = tid; idx < BT * 64; idx += 256)
            sS[idx >> 6][idx & 63] = z[(size_t)(b0 + (idx >> 6)) * DIM + d0 + (idx & 63)];
        for (int idx = tid; idx < 64 * VT; idx += 256)
            sWv[idx >> 7][idx & 127] = Wv[(size_t)(d0 + (idx >> 7)) * VOCAB + v0 + (idx & 127)];
        __syncthreads();

        #pragma unroll 4
        for (int d = 0; d < 64; ++d) {
            const ulonglong2 w2 = *(const ulonglong2*)&sWv[d][vb * 4];
            #pragma unroll
            for (int i = 0; i < 4; ++i) {
                const float u = sS[bg * 4 + i][d];
                const unsigned long long uu = pack2(u, u);
                ffma2(acc[i][0], uu, w2.x);
                ffma2(acc[i][1], uu, w2.y);
            }
        }
    }

    const float4 bvv = *(const float4*)&bv[v0 + vb * 4];
    #pragma unroll
    for (int i = 0; i < 4; ++i) {
        const float2 p0 = unpack2(acc[i][0]);
        const float2 p1 = unpack2(acc[i][1]);
        float4 r = make_float4(p0.x + bvv.x, p0.y + bvv.y,
                               p1.x + bvv.z, p1.y + bvv.w);
        *(float4*)&L[(size_t)(b0 + bg * 4 + i) * VOCAB + v0 + vb * 4] = r;
    }
}

// ---------------------------------------------------------------------------
// In-place log_softmax over each row of L [BATCH][VOCAB]
// ---------------------------------------------------------------------------
__global__ __launch_bounds__(256) void logsoftmax_kernel(float* __restrict__ L)
{
    const int b   = blockIdx.x;
    const int tid = threadIdx.x;
    float* row = L + (size_t)b * VOCAB;
    __shared__ float red[8];

    float m = -1e30f;
    for (int i = tid * 4; i < VOCAB; i += 1024) {
        const float4 v = *(const float4*)&row[i];
        m = fmaxf(m, fmaxf(fmaxf(v.x, v.y), fmaxf(v.z, v.w)));
    }
    #pragma unroll
    for (int o = 16; o; o >>= 1) m = fmaxf(m, __shfl_xor_sync(0xffffffffu, m, o));
    if ((tid & 31) == 0) red[tid >> 5] = m;
    __syncthreads();
    float M = red[0];
    #pragma unroll
    for (int j = 1; j < 8; ++j) M = fmaxf(M, red[j]);
    __syncthreads();

    float s = 0.f;
    for (int i = tid * 4; i < VOCAB; i += 1024) {
        const float4 v = *(const float4*)&row[i];
        s += expf(v.x - M) + expf(v.y - M) + expf(v.z - M) + expf(v.w - M);
    }
    #pragma unroll
    for (int o = 16; o; o >>= 1) s += __shfl_xor_sync(0xffffffffu, s, o);
    if ((tid & 31) == 0) red[tid >> 5] = s;
    __syncthreads();
    float S = 0.f;
    #pragma unroll
    for (int j = 0; j < 8; ++j) S += red[j];
    const float lse = M + logf(S);

    for (int i = tid * 4; i < VOCAB; i += 1024) {
        float4 v = *(const float4*)&row[i];
        v.x -= lse; v.y -= lse; v.z -= lse; v.w -= lse;
        *(float4*)&row[i] = v;
    }
}

// ---------------------------------------------------------------------------
// kernel_launch — 4 graph nodes
// Inputs: 0 hidden [B,1,D] | 1 tokens [B,T] int | 2 emb_out [V,D] | 3 W_dt [2D,D]
//         4 b_dt [D] | 5 gamma [D] | 6 beta [D] | 7 W_v [D,V] | 8 b_v [V]
// Output: [ z (B*D) | y (B*V) ] f32
// ---------------------------------------------------------------------------
extern "C" void kernel_launch(void* const* d_in, const int* in_sizes, int n_in,
                              void* d_out, int out_size)
{
    const float* hidden = (const float*)d_in[0];
    const int*   tok    = (const int*)  d_in[1];
    const float* emb    = (const float*)d_in[2];
    const float* Wdt    = (const float*)d_in[3];
    const float* bdt    = (const float*)d_in[4];
    const float* gamma  = (const float*)d_in[5];
    const float* beta   = (const float*)d_in[6];
    const float* Wv     = (const float*)d_in[7];
    const float* bv     = (const float*)d_in[8];

    float* zout = (float*)d_out;
    float* yout = zout + (size_t)BATCH * DIM;

    cudaFuncSetAttribute(rnn_persistent,
                         cudaFuncAttributeMaxDynamicSharedMemorySize, SMEM_BYTES);

    prep_w<<<2 * DIM * DIM / 256, 256>>>(Wdt);
    rnn_persistent<<<NCTA, 256, SMEM_BYTES>>>(hidden, tok, emb, bdt, gamma, beta, zout);
    logits_kernel<<<dim3(VOCAB / VT, BATCH / BT), 256>>>(zout, Wv, bv, yout);
    logsoftmax_kernel<<<BATCH, 256>>>(yout);
}

// round 9
// speedup vs baseline: 1.5983x; 1.2843x over previous
#include <cuda_runtime.h>
#include <cuda_bf16.h>
#include <math.h>
#include <stdint.h>

// Problem constants
#define BATCH 256
#define TLEN  512
#define DIM   1024
#define VOCAB 32000

// Persistent tiling: 256 CTAs; CTA bid -> (kc = bid>>5 of 8, nc = bid&31 of 32)
//   GEMM tile: 256 batch rows x 32 cols x 128 K. LN row b = bid.
#define NK 8
#define NN 32
#define KT 128
#define NT 32
#define NCTA 256
#define CK 32                 // K-chunk per cp.async stage

// Logits tiling
#define VT 128
#define BT 32

// SMEM layout (dynamic):
//  sW: [2 splits][128 k][40 bf16]   stride 80B -> 2 x 10240 = 20480 B
//  sA: [2 bufs][2 splits][256 m][40 bf16] stride 80B -> per split 20480 B
#define SM_W    0
#define W_SPL   10240u
#define SM_A    20480
#define ASTRIDE 80u
#define ASPL    20480u        // per-split (256 rows x 80B)
#define ABUF    40960u        // per-buf (2 splits)
#define SMEM_BYTES (20480 + 2 * 40960)   // 102400

// ---------------------------------------------------------------------------
// Device scratch (static — no cudaMalloc allowed)
// ---------------------------------------------------------------------------
__device__ float         g_P[NK][BATCH][DIM];     // partial sums
__device__ __nv_bfloat16 g_Uhi[BATCH][DIM], g_Ulo[BATCH][DIM];  // u row-major, split
__device__ __nv_bfloat16 g_Hhi[BATCH][DIM], g_Hlo[BATCH][DIM];  // hidden row-major, split
__device__ unsigned g_bar_arrive = 0;
__device__ unsigned g_bar_gen    = 0;

// ---------------------------------------------------------------------------
// PTX helpers
// ---------------------------------------------------------------------------
__device__ __forceinline__ uint32_t smem_u32(const void* p) {
    uint32_t a;
    asm("{ .reg .u64 t; cvta.to.shared.u64 t, %1; cvt.u32.u64 %0, t; }" : "=r"(a) : "l"(p));
    return a;
}
__device__ __forceinline__ void cp_async16(uint32_t dst, const void* src) {
    asm volatile("cp.async.cg.shared.global [%0], [%1], 16;" :: "r"(dst), "l"(src) : "memory");
}
#define CP_COMMIT() asm volatile("cp.async.commit_group;" ::: "memory")
#define CP_WAIT(n)  asm volatile("cp.async.wait_group %0;" :: "n"(n) : "memory")

// non-trans x4 (A fragment, row-major [m][k])
__device__ __forceinline__ void ldm_x4(uint32_t* r, uint32_t addr) {
    asm volatile("ldmatrix.sync.aligned.m8n8.x4.shared.b16 {%0,%1,%2,%3}, [%4];"
                 : "=r"(r[0]), "=r"(r[1]), "=r"(r[2]), "=r"(r[3]) : "r"(addr));
}
// trans x2 (B fragment from W [k][n])
__device__ __forceinline__ void ldm_x2_t(uint32_t* r, uint32_t addr) {
    asm volatile("ldmatrix.sync.aligned.m8n8.x2.trans.shared.b16 {%0,%1}, [%2];"
                 : "=r"(r[0]), "=r"(r[1]) : "r"(addr));
}
__device__ __forceinline__ void mma_bf16(float* c, const uint32_t* a, const uint32_t* b) {
    asm volatile(
        "mma.sync.aligned.m16n8k16.row.col.f32.bf16.bf16.f32 "
        "{%0,%1,%2,%3}, {%4,%5,%6,%7}, {%8,%9}, {%0,%1,%2,%3};"
        : "+f"(c[0]), "+f"(c[1]), "+f"(c[2]), "+f"(c[3])
        : "r"(a[0]), "r"(a[1]), "r"(a[2]), "r"(a[3]), "r"(b[0]), "r"(b[1]));
}
__device__ __forceinline__ uint32_t pack_bf16x2(float a, float b) {
    const __nv_bfloat16 ba = __float2bfloat16(a);
    const __nv_bfloat16 bb = __float2bfloat16(b);
    return (uint32_t)__bfloat16_as_ushort(ba) | ((uint32_t)__bfloat16_as_ushort(bb) << 16);
}

// ---------------------------------------------------------------------------
// Grid-wide barrier (sense-reversing; 256 CTAs, 2/SM co-resident)
// ---------------------------------------------------------------------------
__device__ __forceinline__ void grid_barrier()
{
    __threadfence();
    __syncthreads();
    if (threadIdx.x == 0) {
        unsigned gen = *(volatile unsigned*)&g_bar_gen;
        if (atomicAdd(&g_bar_arrive, 1u) == NCTA - 1u) {
            atomicExch(&g_bar_arrive, 0u);
            __threadfence();
            atomicAdd(&g_bar_gen, 1u);
        } else {
            while (*(volatile unsigned*)&g_bar_gen == gen) { }
        }
        __threadfence();
    }
    __syncthreads();
}

// ---------------------------------------------------------------------------
// W tile load: fp32 Wdt -> smem bf16 hi/lo, [k][n] stride 80B
// ---------------------------------------------------------------------------
__device__ __forceinline__ void load_w(char* smp, const float* __restrict__ Wdt,
                                       int half, int k0, int n0, int tid)
{
    #pragma unroll
    for (int t = 0; t < 16; ++t) {
        const int i = tid + t * 256;      // 0..4095
        const int k = i >> 5;
        const int n = i & 31;
        const float v = Wdt[(size_t)(half * DIM + k0 + k) * DIM + n0 + n];
        const __nv_bfloat16 hi = __float2bfloat16(v);
        const __nv_bfloat16 lo = __float2bfloat16(v - __bfloat162float(hi));
        *(__nv_bfloat16*)(smp + SM_W + (uint32_t)k * ASTRIDE + (uint32_t)n * 2u) = hi;
        *(__nv_bfloat16*)(smp + SM_W + W_SPL + (uint32_t)k * ASTRIDE + (uint32_t)n * 2u) = lo;
    }
}

// cp.async one 32-k chunk of A (hi+lo): 256 rows x 64B x 2 splits = 2048 x 16B
__device__ __forceinline__ void issue_chunk(uint32_t sa_base,
    const __nv_bfloat16* __restrict__ srchi, const __nv_bfloat16* __restrict__ srclo,
    int kglob, int tid)
{
    #pragma unroll
    for (int t = 0; t < 8; ++t) {
        const int i  = tid + t * 256;     // 0..2047
        const int sp = i >> 10;
        const int r  = (i >> 2) & 255;
        const int c  = i & 3;             // 16B column (8 bf16)
        const __nv_bfloat16* src = (sp ? srclo : srchi) + (size_t)r * DIM + kglob + c * 8;
        const uint32_t dst = sa_base + (uint32_t)sp * ASPL + (uint32_t)r * ASTRIDE + (uint32_t)c * 16u;
        cp_async16(dst, src);
    }
    CP_COMMIT();
}

// ---------------------------------------------------------------------------
// Compute one 32-k chunk: 2 ksteps x (2 m-tiles x 4 n-tiles x 3 split products)
// A row-major [m][k] stride 80B (non-trans ldmatrix); W [k][n] stride 80B (trans).
// ---------------------------------------------------------------------------
__device__ __forceinline__ void compute_chunk(uint32_t abase, uint32_t wbase, int kb,
                                              float acc[2][4][4], int lane, int wid)
{
    #pragma unroll
    for (int ks = 0; ks < 2; ++ks) {
        // B fragments
        uint32_t bh[4][2], bl[4][2];
        const uint32_t krow_b = (uint32_t)(kb + ks * 16 + (lane & 15));
        #pragma unroll
        for (int nt = 0; nt < 4; ++nt) {
            ldm_x2_t(bh[nt], wbase + 0u    + krow_b * ASTRIDE + (uint32_t)nt * 16u);
            ldm_x2_t(bl[nt], wbase + W_SPL + krow_b * ASTRIDE + (uint32_t)nt * 16u);
        }
        // A fragments (canonical non-trans m16k16: lane&15 -> row, lane>>4 -> k-half)
        const uint32_t arow = (uint32_t)(wid * 32 + (lane & 15));
        const uint32_t acol = (uint32_t)(ks * 32 + (lane >> 4) * 16);
        uint32_t ah[2][4], al[2][4];
        #pragma unroll
        for (int mt = 0; mt < 2; ++mt) {
            const uint32_t off = (arow + (uint32_t)mt * 16u) * ASTRIDE + acol;
            ldm_x4(ah[mt], abase + off);
            ldm_x4(al[mt], abase + ASPL + off);
        }
        #pragma unroll
        for (int mt = 0; mt < 2; ++mt)
            #pragma unroll
            for (int nt = 0; nt < 4; ++nt) {
                mma_bf16(acc[mt][nt], ah[mt], bh[nt]);
                mma_bf16(acc[mt][nt], ah[mt], bl[nt]);
                mma_bf16(acc[mt][nt], al[mt], bh[nt]);
            }
    }
}

// ---------------------------------------------------------------------------
// One full step GEMM: P[kc][all 256 b][n0..n0+31] over K [k0, k0+128)
// ---------------------------------------------------------------------------
__device__ __forceinline__ void gemm_step_mma(char* smp, uint32_t base,
    const __nv_bfloat16* __restrict__ srchi, const __nv_bfloat16* __restrict__ srclo,
    int k0, int n0, int kc, int tid)
{
    const int lane = tid & 31, wid = tid >> 5;
    float acc[2][4][4];
    #pragma unroll
    for (int mt = 0; mt < 2; ++mt)
        #pragma unroll
        for (int nt = 0; nt < 4; ++nt)
            #pragma unroll
            for (int q = 0; q < 4; ++q) acc[mt][nt][q] = 0.f;

    const uint32_t a0 = base + SM_A;
    const uint32_t a1 = base + SM_A + ABUF;
    const uint32_t wb = base + SM_W;

    issue_chunk(a0, srchi, srclo, k0 + 0 * CK, tid);
    issue_chunk(a1, srchi, srclo, k0 + 1 * CK, tid);

    CP_WAIT(1); __syncthreads();
    compute_chunk(a0, wb, 0 * CK, acc, lane, wid);
    __syncthreads();
    issue_chunk(a0, srchi, srclo, k0 + 2 * CK, tid);

    CP_WAIT(1); __syncthreads();
    compute_chunk(a1, wb, 1 * CK, acc, lane, wid);
    __syncthreads();
    issue_chunk(a1, srchi, srclo, k0 + 3 * CK, tid);

    CP_WAIT(1); __syncthreads();
    compute_chunk(a0, wb, 2 * CK, acc, lane, wid);

    CP_WAIT(0); __syncthreads();
    compute_chunk(a1, wb, 3 * CK, acc, lane, wid);

    // store accumulators -> g_P[kc] (warp wid owns rows wid*32..+31)
    const int r4 = lane >> 2, c2 = (lane & 3) * 2;
    #pragma unroll
    for (int mt = 0; mt < 2; ++mt)
        #pragma unroll
        for (int nt = 0; nt < 4; ++nt) {
            const int r0 = wid * 32 + mt * 16 + r4;
            const int cc = n0 + nt * 8 + c2;
            __stcg((float2*)&g_P[kc][r0][cc],     make_float2(acc[mt][nt][0], acc[mt][nt][1]));
            __stcg((float2*)&g_P[kc][r0 + 8][cc], make_float2(acc[mt][nt][2], acc[mt][nt][3]));
        }
}

// ---------------------------------------------------------------------------
// Persistent scan kernel: init + c precompute + 512 x (HMMA GEMM, LN)
// ---------------------------------------------------------------------------
__global__ __launch_bounds__(256, 2) void rnn_persistent(
    const float* __restrict__ hidden, const int* __restrict__ tok,
    const float* __restrict__ emb,    const float* __restrict__ Wdt,
    const float* __restrict__ bdt,    const float* __restrict__ gamma,
    const float* __restrict__ beta,   float* __restrict__ zout)
{
    extern __shared__ char smp[];
    const uint32_t base = smem_u32(smp);
    __shared__ float red[2][8];

    const int tid = threadIdx.x;
    const int bid = blockIdx.x;
    const int nc = bid & 31, kc = bid >> 5;
    const int n0 = nc * NT,  k0 = kc * KT;
    const int b  = bid;           // LN row
    const int d0 = tid * 4;       // LN channels

    // ---- init: row-major bf16 splits of hidden and u0 ----
    float4 ureg;
    {
        const int tk0 = tok[(size_t)b * TLEN];
        const float4 hv = *(const float4*)&hidden[(size_t)b * DIM + d0];
        const float4 uv = *(const float4*)&emb[(size_t)tk0 * DIM + d0];
        ureg = uv;
        // hidden splits
        {
            const uint32_t h0 = pack_bf16x2(hv.x, hv.y), h1 = pack_bf16x2(hv.z, hv.w);
            __stcg((uint2*)&g_Hhi[b][d0], make_uint2(h0, h1));
            const float lx = hv.x - __bfloat162float(__float2bfloat16(hv.x));
            const float ly = hv.y - __bfloat162float(__float2bfloat16(hv.y));
            const float lz = hv.z - __bfloat162float(__float2bfloat16(hv.z));
            const float lw = hv.w - __bfloat162float(__float2bfloat16(hv.w));
            __stcg((uint2*)&g_Hlo[b][d0], make_uint2(pack_bf16x2(lx, ly), pack_bf16x2(lz, lw)));
        }
        // u0 splits
        {
            const uint32_t h0 = pack_bf16x2(uv.x, uv.y), h1 = pack_bf16x2(uv.z, uv.w);
            __stcg((uint2*)&g_Uhi[b][d0], make_uint2(h0, h1));
            const float lx = uv.x - __bfloat162float(__float2bfloat16(uv.x));
            const float ly = uv.y - __bfloat162float(__float2bfloat16(uv.y));
            const float lz = uv.z - __bfloat162float(__float2bfloat16(uv.z));
            const float lw = uv.w - __bfloat162float(__float2bfloat16(uv.w));
            __stcg((uint2*)&g_Ulo[b][d0], make_uint2(pack_bf16x2(lx, ly), pack_bf16x2(lz, lw)));
        }
    }
    const float4 g4 = *(const float4*)&gamma[d0];
    const float4 b4 = *(const float4*)&beta[d0];

    // ---- c = hidden @ W_bot + b_dt ----
    load_w(smp, Wdt, 1, k0, n0, tid);
    grid_barrier();                     // H/U splits visible everywhere
    gemm_step_mma(smp, base, &g_Hhi[0][0], &g_Hlo[0][0], k0, n0, kc, tid);
    grid_barrier();                     // g_P complete

    float4 creg = *(const float4*)&bdt[d0];
    #pragma unroll
    for (int j = 0; j < NK; ++j) {
        const float4 p = __ldcg((const float4*)&g_P[j][b][d0]);
        creg.x += p.x; creg.y += p.y; creg.z += p.z; creg.w += p.w;
    }

    __syncthreads();
    load_w(smp, Wdt, 0, k0, n0, tid);   // W_top, persistent for the scan
    grid_barrier();                     // P consumed before step 0 overwrites

    // ---- scan ----
    for (int t = 0; t < TLEN; ++t) {
        gemm_step_mma(smp, base, &g_Uhi[0][0], &g_Ulo[0][0], k0, n0, kc, tid);
        grid_barrier();

        // LN: y = C + U + sum_j P[j]
        float4 y = creg;
        y.x += ureg.x; y.y += ureg.y; y.z += ureg.z; y.w += ureg.w;
        #pragma unroll
        for (int j = 0; j < NK; ++j) {
            const float4 p = __ldcg((const float4*)&g_P[j][b][d0]);
            y.x += p.x; y.y += p.y; y.z += p.z; y.w += p.w;
        }

        float s1 = y.x + y.y + y.z + y.w;
        float s2 = y.x*y.x + y.y*y.y + y.z*y.z + y.w*y.w;
        #pragma unroll
        for (int o = 16; o; o >>= 1) {
            s1 += __shfl_xor_sync(0xffffffffu, s1, o);
            s2 += __shfl_xor_sync(0xffffffffu, s2, o);
        }
        if ((tid & 31) == 0) { red[0][tid >> 5] = s1; red[1][tid >> 5] = s2; }
        __syncthreads();
        float t1 = 0.f, t2 = 0.f;
        #pragma unroll
        for (int j = 0; j < 8; ++j) { t1 += red[0][j]; t2 += red[1][j]; }
        __syncthreads();

        const float mean = t1 * (1.f / DIM);
        const float var  = t2 * (1.f / DIM) - mean * mean;
        const float rstd = rsqrtf(var + 1e-5f);

        float4 s;
        s.x = (y.x - mean) * rstd * g4.x + b4.x;
        s.y = (y.y - mean) * rstd * g4.y + b4.y;
        s.z = (y.z - mean) * rstd * g4.z + b4.z;
        s.w = (y.w - mean) * rstd * g4.w + b4.w;

        if (t < TLEN - 1) {
            const int tk = tok[(size_t)b * TLEN + t + 1];
            const float4 e = *(const float4*)&emb[(size_t)tk * DIM + d0];
            const float u0 = s.x + e.x, u1 = s.y + e.y, u2 = s.z + e.z, u3 = s.w + e.w;
            ureg = make_float4(u0, u1, u2, u3);
            __stcg((uint2*)&g_Uhi[b][d0],
                   make_uint2(pack_bf16x2(u0, u1), pack_bf16x2(u2, u3)));
            const float l0 = u0 - __bfloat162float(__float2bfloat16(u0));
            const float l1 = u1 - __bfloat162float(__float2bfloat16(u1));
            const float l2 = u2 - __bfloat162float(__float2bfloat16(u2));
            const float l3 = u3 - __bfloat162float(__float2bfloat16(u3));
            __stcg((uint2*)&g_Ulo[b][d0],
                   make_uint2(pack_bf16x2(l0, l1), pack_bf16x2(l2, l3)));
        } else {
            *(float4*)&zout[(size_t)b * DIM + d0] = s;
        }
        grid_barrier();
    }
}

// ---------------------------------------------------------------------------
// Packed f32x2 helpers (logits kernel)
// ---------------------------------------------------------------------------
__device__ __forceinline__ unsigned long long pack2(float lo, float hi)
{
    unsigned long long r;
    asm("mov.b64 %0, {%1, %2};" : "=l"(r) : "f"(lo), "f"(hi));
    return r;
}
__device__ __forceinline__ float2 unpack2(unsigned long long v)
{
    float2 r;
    asm("mov.b64 {%0, %1}, %2;" : "=f"(r.x), "=f"(r.y) : "l"(v));
    return r;
}
__device__ __forceinline__ void ffma2(unsigned long long& acc,
                                      unsigned long long a, unsigned long long b)
{
    asm("fma.rn.f32x2 %0, %1, %2, %0;" : "+l"(acc) : "l"(a), "l"(b));
}

// ---------------------------------------------------------------------------
// Logits: L[b][v] = sum_d z[b][d] * Wv[d][v] + bv[v]
// ---------------------------------------------------------------------------
__global__ __launch_bounds__(256, 2) void logits_kernel(
    const float* __restrict__ z, const float* __restrict__ Wv,
    const float* __restrict__ bv, float* __restrict__ L)
{
    __shared__ float sS[BT][64];
    __shared__ float sWv[64][VT];

    const int tid = threadIdx.x;
    const int v0  = blockIdx.x * VT;
    const int b0  = blockIdx.y * BT;
    const int vb  = tid & 31;
    const int bg  = tid >> 5;

    unsigned long long acc[4][2];
    #pragma unroll
    for (int i = 0; i < 4; ++i) { acc[i][0] = 0ull; acc[i][1] = 0ull; }

    for (int slab = 0; slab < DIM / 64; ++slab) {
        const int d0 = slab * 64;
        __syncthreads();
        for (int idx = tid; idx < BT * 64; idx += 256)
            sS[idx >> 6][idx & 63] = z[(size_t)(b0 + (idx >> 6)) * DIM + d0 + (idx & 63)];
        for (int idx = tid; idx < 64 * VT; idx += 256)
            sWv[idx >> 7][idx & 127] = Wv[(size_t)(d0 + (idx >> 7)) * VOCAB + v0 + (idx & 127)];
        __syncthreads();

        #pragma unroll 4
        for (int d = 0; d < 64; ++d) {
            const ulonglong2 w2 = *(const ulonglong2*)&sWv[d][vb * 4];
            #pragma unroll
            for (int i = 0; i < 4; ++i) {
                const float u = sS[bg * 4 + i][d];
                const unsigned long long uu = pack2(u, u);
                ffma2(acc[i][0], uu, w2.x);
                ffma2(acc[i][1], uu, w2.y);
            }
        }
    }

    const float4 bvv = *(const float4*)&bv[v0 + vb * 4];
    #pragma unroll
    for (int i = 0; i < 4; ++i) {
        const float2 p0 = unpack2(acc[i][0]);
        const float2 p1 = unpack2(acc[i][1]);
        float4 r = make_float4(p0.x + bvv.x, p0.y + bvv.y,
                               p1.x + bvv.z, p1.y + bvv.w);
        *(float4*)&L[(size_t)(b0 + bg * 4 + i) * VOCAB + v0 + vb * 4] = r;
    }
}

// ---------------------------------------------------------------------------
// In-place log_softmax over each row of L [BATCH][VOCAB]
// ---------------------------------------------------------------------------
__global__ __launch_bounds__(256) void logsoftmax_kernel(float* __restrict__ L)
{
    const int b   = blockIdx.x;
    const int tid = threadIdx.x;
    float* row = L + (size_t)b * VOCAB;
    __shared__ float red[8];

    float m = -1e30f;
    for (int i = tid * 4; i < VOCAB; i += 1024) {
        const float4 v = *(const float4*)&row[i];
        m = fmaxf(m, fmaxf(fmaxf(v.x, v.y), fmaxf(v.z, v.w)));
    }
    #pragma unroll
    for (int o = 16; o; o >>= 1) m = fmaxf(m, __shfl_xor_sync(0xffffffffu, m, o));
    if ((tid & 31) == 0) red[tid >> 5] = m;
    __syncthreads();
    float M = red[0];
    #pragma unroll
    for (int j = 1; j < 8; ++j) M = fmaxf(M, red[j]);
    __syncthreads();

    float s = 0.f;
    for (int i = tid * 4; i < VOCAB; i += 1024) {
        const float4 v = *(const float4*)&row[i];
        s += expf(v.x - M) + expf(v.y - M) + expf(v.z - M) + expf(v.w - M);
    }
    #pragma unroll
    for (int o = 16; o; o >>= 1) s += __shfl_xor_sync(0xffffffffu, s, o);
    if ((tid & 31) == 0) red[tid >> 5] = s;
    __syncthreads();
    float S = 0.f;
    #pragma unroll
    for (int j = 0; j < 8; ++j) S += red[j];
    const float lse = M + logf(S);

    for (int i = tid * 4; i < VOCAB; i += 1024) {
        float4 v = *(const float4*)&row[i];
        v.x -= lse; v.y -= lse; v.z -= lse; v.w -= lse;
        *(float4*)&row[i] = v;
    }
}

// ---------------------------------------------------------------------------
// kernel_launch — 3 graph nodes
// Inputs: 0 hidden [B,1,D] | 1 tokens [B,T] int | 2 emb_out [V,D] | 3 W_dt [2D,D]
//         4 b_dt [D] | 5 gamma [D] | 6 beta [D] | 7 W_v [D,V] | 8 b_v [V]
// Output: [ z (B*D) | y (B*V) ] f32
// ---------------------------------------------------------------------------
extern "C" void kernel_launch(void* const* d_in, const int* in_sizes, int n_in,
                              void* d_out, int out_size)
{
    const float* hidden = (const float*)d_in[0];
    const int*   tok    = (const int*)  d_in[1];
    const float* emb    = (const float*)d_in[2];
    const float* Wdt    = (const float*)d_in[3];
    const float* bdt    = (const float*)d_in[4];
    const float* gamma  = (const float*)d_in[5];
    const float* beta   = (const float*)d_in[6];
    const float* Wv     = (const float*)d_in[7];
    const float* bv     = (const float*)d_in[8];

    float* zout = (float*)d_out;
    float* yout = zout + (size_t)BATCH * DIM;

    cudaFuncSetAttribute(rnn_persistent,
                         cudaFuncAttributeMaxDynamicSharedMemorySize, SMEM_BYTES);

    rnn_persistent<<<NCTA, 256, SMEM_BYTES>>>(hidden, tok, emb, Wdt, bdt, gamma, beta, zout);
    logits_kernel<<<dim3(VOCAB / VT, BATCH / BT), 256>>>(zout, Wv, bv, yout);
    logsoftmax_kernel<<<BATCH, 256>>>(yout);
}

// round 11
// speedup vs baseline: 1.8551x; 1.1606x over previous
#include <cuda_runtime.h>
#include <cuda_bf16.h>
#include <math.h>
#include <stdint.h>

// Problem constants
#define BATCH 256
#define TLEN  512
#define DIM   1024
#define VOCAB 32000

// Persistent tiling: 128 CTAs (1/SM); CTA bid -> (kc = bid>>4 of 8, nc = bid&15 of 16)
//   GEMM tile: 256 batch rows x 64 cols x 128 K.  LN rows: b = 2*bid + (tid>>7).
#define NK 8
#define NN 16
#define KT 128
#define NT 64
#define NCTA 128
#define KC 64                 // K-chunk per cp.async stage (2 per step)

// Logits tiling
#define VT 128
#define BT 32

// SMEM layout (dynamic):
//  sW: [2 splits][128 k][72 bf16]  stride 144B -> 2 x 18432 = 36864 B
//  sA: [2 chunks][2 splits][256 m][72 bf16] stride 144B -> per split 36864 B
#define SM_W    0
#define W_SPL   18432u
#define SM_A    36864
#define ASTRIDE 144u
#define ASPL    36864u        // per-split (256 rows x 144B)
#define ACH     73728u        // per-chunk (2 splits)
#define SMEM_BYTES (36864 + 2 * 73728)   // 184320

// ---------------------------------------------------------------------------
// Device scratch (static — no cudaMalloc allowed)
// ---------------------------------------------------------------------------
__device__ float         g_P[NK][BATCH][DIM];     // partial sums
__device__ __nv_bfloat16 g_Uhi[BATCH][DIM], g_Ulo[BATCH][DIM];  // u row-major, split
__device__ __nv_bfloat16 g_Hhi[BATCH][DIM], g_Hlo[BATCH][DIM];  // hidden row-major, split
__device__ unsigned g_bar_arrive = 0;
__device__ unsigned g_bar_gen    = 0;

// ---------------------------------------------------------------------------
// PTX helpers
// ---------------------------------------------------------------------------
__device__ __forceinline__ uint32_t smem_u32(const void* p) {
    uint32_t a;
    asm("{ .reg .u64 t; cvta.to.shared.u64 t, %1; cvt.u32.u64 %0, t; }" : "=r"(a) : "l"(p));
    return a;
}
__device__ __forceinline__ void cp_async16(uint32_t dst, const void* src) {
    asm volatile("cp.async.cg.shared.global [%0], [%1], 16;" :: "r"(dst), "l"(src) : "memory");
}
#define CP_COMMIT() asm volatile("cp.async.commit_group;" ::: "memory")
#define CP_WAIT(n)  asm volatile("cp.async.wait_group %0;" :: "n"(n) : "memory")

// non-trans x4 (A fragment, row-major [m][k])
__device__ __forceinline__ void ldm_x4(uint32_t* r, uint32_t addr) {
    asm volatile("ldmatrix.sync.aligned.m8n8.x4.shared.b16 {%0,%1,%2,%3}, [%4];"
                 : "=r"(r[0]), "=r"(r[1]), "=r"(r[2]), "=r"(r[3]) : "r"(addr));
}
// trans x2 (B fragment from W [k][n])
__device__ __forceinline__ void ldm_x2_t(uint32_t* r, uint32_t addr) {
    asm volatile("ldmatrix.sync.aligned.m8n8.x2.trans.shared.b16 {%0,%1}, [%2];"
                 : "=r"(r[0]), "=r"(r[1]) : "r"(addr));
}
__device__ __forceinline__ void mma_bf16(float* c, const uint32_t* a, const uint32_t* b) {
    asm volatile(
        "mma.sync.aligned.m16n8k16.row.col.f32.bf16.bf16.f32 "
        "{%0,%1,%2,%3}, {%4,%5,%6,%7}, {%8,%9}, {%0,%1,%2,%3};"
        : "+f"(c[0]), "+f"(c[1]), "+f"(c[2]), "+f"(c[3])
        : "r"(a[0]), "r"(a[1]), "r"(a[2]), "r"(a[3]), "r"(b[0]), "r"(b[1]));
}
__device__ __forceinline__ uint32_t pack_bf16x2(float a, float b) {
    const __nv_bfloat16 ba = __float2bfloat16(a);
    const __nv_bfloat16 bb = __float2bfloat16(b);
    return (uint32_t)__bfloat16_as_ushort(ba) | ((uint32_t)__bfloat16_as_ushort(bb) << 16);
}
// split 8 fp32 channels -> bf16 hi/lo, store as 2x16B (.cg)
__device__ __forceinline__ void split_store8(__nv_bfloat16* hp, __nv_bfloat16* lp,
                                             const float* v)
{
    uint32_t h[4], l[4];
    #pragma unroll
    for (int q = 0; q < 4; ++q) {
        const float a = v[2*q], b = v[2*q+1];
        h[q] = pack_bf16x2(a, b);
        const float la = a - __bfloat162float(__float2bfloat16(a));
        const float lb = b - __bfloat162float(__float2bfloat16(b));
        l[q] = pack_bf16x2(la, lb);
    }
    __stcg((uint4*)hp, make_uint4(h[0], h[1], h[2], h[3]));
    __stcg((uint4*)lp, make_uint4(l[0], l[1], l[2], l[3]));
}

// ---------------------------------------------------------------------------
// Grid-wide barrier (sense-reversing; 128 CTAs, 1/SM, all co-resident)
// ---------------------------------------------------------------------------
__device__ __forceinline__ void grid_barrier()
{
    __threadfence();
    __syncthreads();
    if (threadIdx.x == 0) {
        unsigned gen = *(volatile unsigned*)&g_bar_gen;
        if (atomicAdd(&g_bar_arrive, 1u) == NCTA - 1u) {
            atomicExch(&g_bar_arrive, 0u);
            __threadfence();
            atomicAdd(&g_bar_gen, 1u);
        } else {
            while (*(volatile unsigned*)&g_bar_gen == gen) { }
        }
        __threadfence();
    }
    __syncthreads();
}

// ---------------------------------------------------------------------------
// W tile load: fp32 Wdt -> smem bf16 hi/lo, [k][n] stride 144B
// ---------------------------------------------------------------------------
__device__ __forceinline__ void load_w(char* smp, const float* __restrict__ Wdt,
                                       int half, int k0, int n0, int tid)
{
    #pragma unroll
    for (int t = 0; t < 32; ++t) {
        const int i = tid + t * 256;      // 0..8191
        const int k = i >> 6;
        const int n = i & 63;
        const float v = Wdt[(size_t)(half * DIM + k0 + k) * DIM + n0 + n];
        const __nv_bfloat16 hi = __float2bfloat16(v);
        const __nv_bfloat16 lo = __float2bfloat16(v - __bfloat162float(hi));
        *(__nv_bfloat16*)(smp + SM_W + (uint32_t)k * ASTRIDE + (uint32_t)n * 2u) = hi;
        *(__nv_bfloat16*)(smp + SM_W + W_SPL + (uint32_t)k * ASTRIDE + (uint32_t)n * 2u) = lo;
    }
}

// cp.async one 64-k chunk of A (hi+lo): 256 rows x 128B x 2 splits = 4096 x 16B
__device__ __forceinline__ void issue_chunk(uint32_t sa_base,
    const __nv_bfloat16* __restrict__ srchi, const __nv_bfloat16* __restrict__ srclo,
    int kglob, int tid)
{
    #pragma unroll
    for (int t = 0; t < 16; ++t) {
        const int i  = tid + t * 256;     // 0..4095
        const int sp = i >> 11;           // 0..1 (2048 transfers per split)
        const int r  = (i >> 3) & 255;    // row 0..255
        const int c  = i & 7;             // 16B column; 8 cols x 16B = 128B = 64 bf16
        const __nv_bfloat16* src = (sp ? srclo : srchi) + (size_t)r * DIM + kglob + c * 8;
        const uint32_t dst = sa_base + (uint32_t)sp * ASPL + (uint32_t)r * ASTRIDE + (uint32_t)c * 16u;
        cp_async16(dst, src);
    }
    CP_COMMIT();
}

// ---------------------------------------------------------------------------
// Compute one 64-k chunk: 4 ksteps x (2 m-tiles x 8 n-tiles x 3 split products)
// A row-major [m][k] stride 144B (non-trans); W [k][n] stride 144B (trans).
// ---------------------------------------------------------------------------
__device__ __forceinline__ void compute_chunk(uint32_t abase, uint32_t wbase, int c,
                                              float acc[2][8][4], int lane, int wid)
{
    #pragma unroll
    for (int ks = 0; ks < 4; ++ks) {
        // B fragments (k-row within the CTA's full K=128 W tile)
        uint32_t bh[8][2], bl[8][2];
        const uint32_t krow_b = (uint32_t)(c * KC + ks * 16 + (lane & 15));
        #pragma unroll
        for (int nt = 0; nt < 8; ++nt) {
            ldm_x2_t(bh[nt], wbase + 0u    + krow_b * ASTRIDE + (uint32_t)nt * 16u);
            ldm_x2_t(bl[nt], wbase + W_SPL + krow_b * ASTRIDE + (uint32_t)nt * 16u);
        }
        // A fragments (within-chunk k 0..63)
        const uint32_t arow = (uint32_t)(wid * 32 + (lane & 15));
        const uint32_t acol = (uint32_t)(ks * 32 + (lane >> 4) * 16);
        uint32_t ah[2][4], al[2][4];
        #pragma unroll
        for (int mt = 0; mt < 2; ++mt) {
            const uint32_t off = (arow + (uint32_t)mt * 16u) * ASTRIDE + acol;
            ldm_x4(ah[mt], abase + off);
            ldm_x4(al[mt], abase + ASPL + off);
        }
        #pragma unroll
        for (int mt = 0; mt < 2; ++mt)
            #pragma unroll
            for (int nt = 0; nt < 8; ++nt) {
                mma_bf16(acc[mt][nt], ah[mt], bh[nt]);
                mma_bf16(acc[mt][nt], ah[mt], bl[nt]);
                mma_bf16(acc[mt][nt], al[mt], bh[nt]);
            }
    }
}

// ---------------------------------------------------------------------------
// One full step GEMM: P[kc][256 b][n0..n0+63] over K [k0, k0+128)
// Both 64-k chunks issued up front; only 2 waits/syncs per step.
// ---------------------------------------------------------------------------
__device__ __forceinline__ void gemm_step_mma(char* smp, uint32_t base,
    const __nv_bfloat16* __restrict__ srchi, const __nv_bfloat16* __restrict__ srclo,
    int k0, int n0, int kc, int tid)
{
    const int lane = tid & 31, wid = tid >> 5;
    float acc[2][8][4];
    #pragma unroll
    for (int mt = 0; mt < 2; ++mt)
        #pragma unroll
        for (int nt = 0; nt < 8; ++nt)
            #pragma unroll
            for (int q = 0; q < 4; ++q) acc[mt][nt][q] = 0.f;

    const uint32_t a0 = base + SM_A;
    const uint32_t a1 = base + SM_A + ACH;
    const uint32_t wb = base + SM_W;

    issue_chunk(a0, srchi, srclo, k0 + 0 * KC, tid);
    issue_chunk(a1, srchi, srclo, k0 + 1 * KC, tid);

    CP_WAIT(1); __syncthreads();
    compute_chunk(a0, wb, 0, acc, lane, wid);
    CP_WAIT(0); __syncthreads();
    compute_chunk(a1, wb, 1, acc, lane, wid);

    // store accumulators -> g_P[kc] (warp wid owns rows wid*32..+31)
    const int r4 = lane >> 2, c2 = (lane & 3) * 2;
    #pragma unroll
    for (int mt = 0; mt < 2; ++mt)
        #pragma unroll
        for (int nt = 0; nt < 8; ++nt) {
            const int r0 = wid * 32 + mt * 16 + r4;
            const int cc = n0 + nt * 8 + c2;
            __stcg((float2*)&g_P[kc][r0][cc],     make_float2(acc[mt][nt][0], acc[mt][nt][1]));
            __stcg((float2*)&g_P[kc][r0 + 8][cc], make_float2(acc[mt][nt][2], acc[mt][nt][3]));
        }
}

// ---------------------------------------------------------------------------
// Persistent scan kernel: init + c precompute + 512 x (HMMA GEMM, LN)
// ---------------------------------------------------------------------------
__global__ __launch_bounds__(256) void rnn_persistent(
    const float* __restrict__ hidden, const int* __restrict__ tok,
    const float* __restrict__ emb,    const float* __restrict__ Wdt,
    const float* __restrict__ bdt,    const float* __restrict__ gamma,
    const float* __restrict__ beta,   float* __restrict__ zout)
{
    extern __shared__ char smp[];
    const uint32_t base = smem_u32(smp);
    __shared__ float red[2][2][4];   // [row][stat][warp-of-row]

    const int tid = threadIdx.x;
    const int bid = blockIdx.x;
    const int nc = bid & 15, kc = bid >> 4;
    const int n0 = nc * NT,  k0 = kc * KT;

    // LN role: 2 rows per CTA
    const int row_sel = tid >> 7;
    const int b  = bid * 2 + row_sel;
    const int lt = tid & 127;
    const int d0 = lt * 8;
    const int wr = (tid >> 5) & 3;

    // ---- init: row-major bf16 splits of hidden and u0 (8 channels/thread) ----
    float ur[8], gm[8], bt[8];
    {
        const int tk0 = tok[(size_t)b * TLEN];
        float hv[8];
        const float4 h0 = *(const float4*)&hidden[(size_t)b * DIM + d0];
        const float4 h1 = *(const float4*)&hidden[(size_t)b * DIM + d0 + 4];
        hv[0]=h0.x; hv[1]=h0.y; hv[2]=h0.z; hv[3]=h0.w;
        hv[4]=h1.x; hv[5]=h1.y; hv[6]=h1.z; hv[7]=h1.w;
        const float4 u0 = *(const float4*)&emb[(size_t)tk0 * DIM + d0];
        const float4 u1 = *(const float4*)&emb[(size_t)tk0 * DIM + d0 + 4];
        ur[0]=u0.x; ur[1]=u0.y; ur[2]=u0.z; ur[3]=u0.w;
        ur[4]=u1.x; ur[5]=u1.y; ur[6]=u1.z; ur[7]=u1.w;
        split_store8(&g_Hhi[b][d0], &g_Hlo[b][d0], hv);
        split_store8(&g_Uhi[b][d0], &g_Ulo[b][d0], ur);
        const float4 g0 = *(const float4*)&gamma[d0];
        const float4 g1 = *(const float4*)&gamma[d0 + 4];
        gm[0]=g0.x; gm[1]=g0.y; gm[2]=g0.z; gm[3]=g0.w;
        gm[4]=g1.x; gm[5]=g1.y; gm[6]=g1.z; gm[7]=g1.w;
        const float4 b0 = *(const float4*)&beta[d0];
        const float4 b1 = *(const float4*)&beta[d0 + 4];
        bt[0]=b0.x; bt[1]=b0.y; bt[2]=b0.z; bt[3]=b0.w;
        bt[4]=b1.x; bt[5]=b1.y; bt[6]=b1.z; bt[7]=b1.w;
    }

    // ---- c = hidden @ W_bot + b_dt ----
    load_w(smp, Wdt, 1, k0, n0, tid);
    grid_barrier();                     // H/U splits visible everywhere
    gemm_step_mma(smp, base, &g_Hhi[0][0], &g_Hlo[0][0], k0, n0, kc, tid);
    grid_barrier();                     // g_P complete

    float cre[8];
    {
        #pragma unroll
        for (int j = 0; j < 8; ++j) cre[j] = 0.f;
        #pragma unroll
        for (int j = 0; j < NK; ++j) {
            const float4 p0 = __ldcg((const float4*)&g_P[j][b][d0]);
            const float4 p1 = __ldcg((const float4*)&g_P[j][b][d0 + 4]);
            cre[0] += p0.x; cre[1] += p0.y; cre[2] += p0.z; cre[3] += p0.w;
            cre[4] += p1.x; cre[5] += p1.y; cre[6] += p1.z; cre[7] += p1.w;
        }
        const float4 bd0 = *(const float4*)&bdt[d0];
        const float4 bd1 = *(const float4*)&bdt[d0 + 4];
        cre[0]+=bd0.x; cre[1]+=bd0.y; cre[2]+=bd0.z; cre[3]+=bd0.w;
        cre[4]+=bd1.x; cre[5]+=bd1.y; cre[6]+=bd1.z; cre[7]+=bd1.w;
    }

    __syncthreads();
    load_w(smp, Wdt, 0, k0, n0, tid);   // W_top, persistent for the scan
    grid_barrier();                     // P consumed before step 0 overwrites

    // ---- scan ----
    for (int t = 0; t < TLEN; ++t) {
        // prefetch next-token embedding
        float ev[8];
        if (t < TLEN - 1) {
            const int tkn = tok[(size_t)b * TLEN + t + 1];
            const float4 e0 = *(const float4*)&emb[(size_t)tkn * DIM + d0];
            const float4 e1 = *(const float4*)&emb[(size_t)tkn * DIM + d0 + 4];
            ev[0]=e0.x; ev[1]=e0.y; ev[2]=e0.z; ev[3]=e0.w;
            ev[4]=e1.x; ev[5]=e1.y; ev[6]=e1.z; ev[7]=e1.w;
        }

        gemm_step_mma(smp, base, &g_Uhi[0][0], &g_Ulo[0][0], k0, n0, kc, tid);
        grid_barrier();

        // LN: y = C + U + sum_j P[j]
        float y[8];
        #pragma unroll
        for (int j = 0; j < 8; ++j) y[j] = cre[j] + ur[j];
        #pragma unroll
        for (int j = 0; j < NK; ++j) {
            const float4 p0 = __ldcg((const float4*)&g_P[j][b][d0]);
            const float4 p1 = __ldcg((const float4*)&g_P[j][b][d0 + 4]);
            y[0] += p0.x; y[1] += p0.y; y[2] += p0.z; y[3] += p0.w;
            y[4] += p1.x; y[5] += p1.y; y[6] += p1.z; y[7] += p1.w;
        }

        float s1 = 0.f, s2 = 0.f;
        #pragma unroll
        for (int j = 0; j < 8; ++j) { s1 += y[j]; s2 += y[j] * y[j]; }
        #pragma unroll
        for (int o = 16; o; o >>= 1) {
            s1 += __shfl_xor_sync(0xffffffffu, s1, o);
            s2 += __shfl_xor_sync(0xffffffffu, s2, o);
        }
        if ((tid & 31) == 0) { red[row_sel][0][wr] = s1; red[row_sel][1][wr] = s2; }
        __syncthreads();
        float t1 = 0.f, t2 = 0.f;
        #pragma unroll
        for (int j = 0; j < 4; ++j) {
            t1 += red[row_sel][0][j];
            t2 += red[row_sel][1][j];
        }
        __syncthreads();

        const float mean = t1 * (1.f / DIM);
        const float var  = t2 * (1.f / DIM) - mean * mean;
        const float rstd = rsqrtf(var + 1e-5f);

        float sv[8];
        #pragma unroll
        for (int j = 0; j < 8; ++j)
            sv[j] = (y[j] - mean) * rstd * gm[j] + bt[j];

        if (t < TLEN - 1) {
            float un[8];
            #pragma unroll
            for (int j = 0; j < 8; ++j) { un[j] = sv[j] + ev[j]; ur[j] = un[j]; }
            split_store8(&g_Uhi[b][d0], &g_Ulo[b][d0], un);
        } else {
            *(float4*)&zout[(size_t)b * DIM + d0] =
                make_float4(sv[0], sv[1], sv[2], sv[3]);
            *(float4*)&zout[(size_t)b * DIM + d0 + 4] =
                make_float4(sv[4], sv[5], sv[6], sv[7]);
        }
        grid_barrier();
    }
}

// ---------------------------------------------------------------------------
// Packed f32x2 helpers (logits kernel)
// ---------------------------------------------------------------------------
__device__ __forceinline__ unsigned long long pack2(float lo, float hi)
{
    unsigned long long r;
    asm("mov.b64 %0, {%1, %2};" : "=l"(r) : "f"(lo), "f"(hi));
    return r;
}
__device__ __forceinline__ float2 unpack2(unsigned long long v)
{
    float2 r;
    asm("mov.b64 {%0, %1}, %2;" : "=f"(r.x), "=f"(r.y) : "l"(v));
    return r;
}
__device__ __forceinline__ void ffma2(unsigned long long& acc,
                                      unsigned long long a, unsigned long long b)
{
    asm("fma.rn.f32x2 %0, %1, %2, %0;" : "+l"(acc) : "l"(a), "l"(b));
}

// ---------------------------------------------------------------------------
// Logits: L[b][v] = sum_d z[b][d] * Wv[d][v] + bv[v]
// ---------------------------------------------------------------------------
__global__ __launch_bounds__(256, 2) void logits_kernel(
    const float* __restrict__ z, const float* __restrict__ Wv,
    const float* __restrict__ bv, float* __restrict__ L)
{
    __shared__ float sS[BT][64];
    __shared__ float sWv[64][VT];

    const int tid = threadIdx.x;
    const int v0  = blockIdx.x * VT;
    const int b0  = blockIdx.y * BT;
    const int vb  = tid & 31;
    const int bg  = tid >> 5;

    unsigned long long acc[4][2];
    #pragma unroll
    for (int i = 0; i < 4; ++i) { acc[i][0] = 0ull; acc[i][1] = 0ull; }

    for (int slab = 0; slab < DIM / 64; ++slab) {
        const int d0 = slab * 64;
        __syncthreads();
        for (int idx = tid; idx < BT * 64; idx += 256)
            sS[idx >> 6][idx & 63] = z[(size_t)(b0 + (idx >> 6)) * DIM + d0 + (idx & 63)];
        for (int idx = tid; idx < 64 * VT; idx += 256)
            sWv[idx >> 7][idx & 127] = Wv[(size_t)(d0 + (idx >> 7)) * VOCAB + v0 + (idx & 127)];
        __syncthreads();

        #pragma unroll 4
        for (int d = 0; d < 64; ++d) {
            const ulonglong2 w2 = *(const ulonglong2*)&sWv[d][vb * 4];
            #pragma unroll
            for (int i = 0; i < 4; ++i) {
                const float u = sS[bg * 4 + i][d];
                const unsigned long long uu = pack2(u, u);
                ffma2(acc[i][0], uu, w2.x);
                ffma2(acc[i][1], uu, w2.y);
            }
        }
    }

    const float4 bvv = *(const float4*)&bv[v0 + vb * 4];
    #pragma unroll
    for (int i = 0; i < 4; ++i) {
        const float2 p0 = unpack2(acc[i][0]);
        const float2 p1 = unpack2(acc[i][1]);
        float4 r = make_float4(p0.x + bvv.x, p0.y + bvv.y,
                               p1.x + bvv.z, p1.y + bvv.w);
        *(float4*)&L[(size_t)(b0 + bg * 4 + i) * VOCAB + v0 + vb * 4] = r;
    }
}

// ---------------------------------------------------------------------------
// In-place log_softmax over each row of L [BATCH][VOCAB]
// ---------------------------------------------------------------------------
__global__ __launch_bounds__(256) void logsoftmax_kernel(float* __restrict__ L)
{
    const int b   = blockIdx.x;
    const int tid = threadIdx.x;
    float* row = L + (size_t)b * VOCAB;
    __shared__ float red[8];

    float m = -1e30f;
    for (int i = tid * 4; i < VOCAB; i += 1024) {
        const float4 v = *(const float4*)&row[i];
        m = fmaxf(m, fmaxf(fmaxf(v.x, v.y), fmaxf(v.z, v.w)));
    }
    #pragma unroll
    for (int o = 16; o; o >>= 1) m = fmaxf(m, __shfl_xor_sync(0xffffffffu, m, o));
    if ((tid & 31) == 0) red[tid >> 5] = m;
    __syncthreads();
    float M = red[0];
    #pragma unroll
    for (int j = 1; j < 8; ++j) M = fmaxf(M, red[j]);
    __syncthreads();

    float s = 0.f;
    for (int i = tid * 4; i < VOCAB; i += 1024) {
        const float4 v = *(const float4*)&row[i];
        s += expf(v.x - M) + expf(v.y - M) + expf(v.z - M) + expf(v.w - M);
    }
    #pragma unroll
    for (int o = 16; o; o >>= 1) s += __shfl_xor_sync(0xffffffffu, s, o);
    if ((tid & 31) == 0) red[tid >> 5] = s;
    __syncthreads();
    float S = 0.f;
    #pragma unroll
    for (int j = 0; j < 8; ++j) S += red[j];
    const float lse = M + logf(S);

    for (int i = tid * 4; i < VOCAB; i += 1024) {
        float4 v = *(const float4*)&row[i];
        v.x -= lse; v.y -= lse; v.z -= lse; v.w -= lse;
        *(float4*)&row[i] = v;
    }
}

// ---------------------------------------------------------------------------
// kernel_launch — 3 graph nodes
// Inputs: 0 hidden [B,1,D] | 1 tokens [B,T] int | 2 emb_out [V,D] | 3 W_dt [2D,D]
//         4 b_dt [D] | 5 gamma [D] | 6 beta [D] | 7 W_v [D,V] | 8 b_v [V]
// Output: [ z (B*D) | y (B*V) ] f32
// ---------------------------------------------------------------------------
extern "C" void kernel_launch(void* const* d_in, const int* in_sizes, int n_in,
                              void* d_out, int out_size)
{
    const float* hidden = (const float*)d_in[0];
    const int*   tok    = (const int*)  d_in[1];
    const float* emb    = (const float*)d_in[2];
    const float* Wdt    = (const float*)d_in[3];
    const float* bdt    = (const float*)d_in[4];
    const float* gamma  = (const float*)d_in[5];
    const float* beta   = (const float*)d_in[6];
    const float* Wv     = (const float*)d_in[7];
    const float* bv     = (const float*)d_in[8];

    float* zout = (float*)d_out;
    float* yout = zout + (size_t)BATCH * DIM;

    cudaFuncSetAttribute(rnn_persistent,
                         cudaFuncAttributeMaxDynamicSharedMemorySize, SMEM_BYTES);

    rnn_persistent<<<NCTA, 256, SMEM_BYTES>>>(hidden, tok, emb, Wdt, bdt, gamma, beta, zout);
    logits_kernel<<<dim3(VOCAB / VT, BATCH / BT), 256>>>(zout, Wv, bv, yout);
    logsoftmax_kernel<<<BATCH, 256>>>(yout);
}